// round 6
// baseline (speedup 1.0000x reference)
#include <cuda_runtime.h>
#include <math.h>

#define BB     2
#define SEQ    1024
#define DIM    1024
#define HEADS  8
#define DH     128
#define MEMN   1024
#define LMEMN  256
#define KVL    2304          // LMEM + MEM + SEQ
#define DEPTH  4
#define VOCAB  32000
#define FFD    4096

// ---------------- scratch (allocation-free: __device__ globals) ----------------
__device__ float g_h[BB*SEQ*DIM];                  // residual stream        (8 MB)
__device__ float g_norm[BB*SEQ*DIM];               // LN output / memnet nl  (8 MB)
__device__ float g_q[BB*SEQ*DIM];                  // Q / memnet q           (8 MB)
__device__ float g_kvin[DEPTH*BB*KVL*DIM];         // kv_in                  (75.5 MB)
__device__ float g_kv[DEPTH*BB*KVL*2*DIM];         // kv = kv_in @ wkv       (151 MB)
__device__ float g_tmp[BB*SEQ*DIM];                // attn out / memnet out  (8 MB)
__device__ float g_ffmid[BB*SEQ*FFD];              // FF hidden              (33.5 MB)
__device__ float g_km[DEPTH*BB*DIM];               // memnet k col max*S
__device__ float g_ki[DEPTH*BB*DIM];               // memnet k col 1/sumexp
__device__ float g_ctx[DEPTH*BB*HEADS*DH*DH];      // memnet ctx             (4 MB)

// ---------------- embedding ----------------
__global__ void embed_k(const int* __restrict__ X, const float* __restrict__ E,
                        float* __restrict__ H)
{
    const int row = blockIdx.x;
    const int tok = X[row];
    const float4* src = (const float4*)(E + (size_t)tok * DIM);
    float4* dst = (float4*)(H + (size_t)row * DIM);
    dst[threadIdx.x] = src[threadIdx.x];
}

// ---------------- LayerNorm over last dim (1024), optional affine ----------------
__global__ __launch_bounds__(256) void ln_k(const float* __restrict__ X,
                                            const float* __restrict__ G,
                                            const float* __restrict__ Bp,
                                            float* __restrict__ Y)
{
    const int tid = threadIdx.x;
    const float4 v = ((const float4*)(X + (size_t)blockIdx.x * DIM))[tid];
    __shared__ float red[8];
    float s = v.x + v.y + v.z + v.w;
#pragma unroll
    for (int off = 16; off; off >>= 1) s += __shfl_xor_sync(0xffffffffu, s, off);
    if ((tid & 31) == 0) red[tid >> 5] = s;
    __syncthreads();
    if (tid == 0) {
        float t = 0.f;
#pragma unroll
        for (int r = 0; r < 8; r++) t += red[r];
        red[0] = t * (1.f / DIM);
    }
    __syncthreads();
    const float mu = red[0];
    __syncthreads();
    const float dx = v.x - mu, dy = v.y - mu, dz = v.z - mu, dw = v.w - mu;
    float ss = dx*dx + dy*dy + dz*dz + dw*dw;
#pragma unroll
    for (int off = 16; off; off >>= 1) ss += __shfl_xor_sync(0xffffffffu, ss, off);
    if ((tid & 31) == 0) red[tid >> 5] = ss;
    __syncthreads();
    if (tid == 0) {
        float t = 0.f;
#pragma unroll
        for (int r = 0; r < 8; r++) t += red[r];
        red[0] = rsqrtf(t * (1.f / DIM) + 1e-5f);
    }
    __syncthreads();
    const float rstd = red[0];
    float4 o;
    o.x = dx * rstd; o.y = dy * rstd; o.z = dz * rstd; o.w = dw * rstd;
    if (G != nullptr) {
        const float4 g4 = ((const float4*)G)[tid];
        const float4 b4 = ((const float4*)Bp)[tid];
        o.x = o.x * g4.x + b4.x;
        o.y = o.y * g4.y + b4.y;
        o.z = o.z * g4.z + b4.z;
        o.w = o.w * g4.w + b4.w;
    }
    ((float4*)(Y + (size_t)blockIdx.x * DIM))[tid] = o;
}

// ---------------- generic SGEMM: C = act(A@B * alpha + bias) + residual ----------------
// 128x128 block tile, BK=8, 8x8 per thread, 256 threads.
// Requires M%128==0, N%128==0, K%8==0 (true for every call here).
template<bool BIAS, bool RES, bool GELU_ACT, bool ALPHA>
__global__ __launch_bounds__(256, 2) void sgemm_k(
    const float* __restrict__ A, const float* __restrict__ Bm,
    const float* __restrict__ bias, const float* __restrict__ R,
    float* __restrict__ C, int M, int N, int K,
    const float* __restrict__ alphaPtr)
{
    __shared__ float As[8][128];
    __shared__ float Bs[8][128];
    const int tid = threadIdx.x;
    const float* Ab = A + (size_t)blockIdx.y * 128 * K;
    const float* Bb = Bm + (size_t)blockIdx.x * 128;
    const int aRow = tid >> 1, aCol = (tid & 1) * 4;
    const int bRow = tid >> 5, bCol = (tid & 31) * 4;
    const int tx = tid & 15, ty = tid >> 4;
    float acc[8][8];
#pragma unroll
    for (int a = 0; a < 8; a++)
#pragma unroll
        for (int b = 0; b < 8; b++) acc[a][b] = 0.f;

    for (int k0 = 0; k0 < K; k0 += 8) {
        const float4 a4 = *(const float4*)(Ab + (size_t)aRow * K + k0 + aCol);
        As[aCol + 0][aRow] = a4.x;
        As[aCol + 1][aRow] = a4.y;
        As[aCol + 2][aRow] = a4.z;
        As[aCol + 3][aRow] = a4.w;
        *(float4*)(&Bs[bRow][bCol]) =
            *(const float4*)(Bb + (size_t)(k0 + bRow) * N + bCol);
        __syncthreads();
#pragma unroll
        for (int kk = 0; kk < 8; kk++) {
            float ra[8], rb[8];
#pragma unroll
            for (int a = 0; a < 8; a++) ra[a] = As[kk][ty * 8 + a];
#pragma unroll
            for (int b = 0; b < 8; b++) rb[b] = Bs[kk][tx * 8 + b];
#pragma unroll
            for (int a = 0; a < 8; a++)
#pragma unroll
                for (int b = 0; b < 8; b++) acc[a][b] += ra[a] * rb[b];
        }
        __syncthreads();
    }

    float alpha = 1.f;
    if (ALPHA) alpha = *alphaPtr;
    const int colBase = blockIdx.x * 128 + tx * 8;
    const size_t rowBase = (size_t)blockIdx.y * 128 + ty * 8;
#pragma unroll
    for (int a = 0; a < 8; a++) {
        const size_t off = (rowBase + a) * (size_t)N + colBase;
#pragma unroll
        for (int b = 0; b < 8; b++) {
            float v = acc[a][b];
            if (ALPHA) v *= alpha;
            if (BIAS) v += bias[colBase + b];
            if (GELU_ACT) v = 0.5f * v * (1.f + erff(v * 0.70710678118654752440f));
            if (RES) v += R[off + b];
            C[off + b] = v;
        }
    }
}

// ---------------- self-attention (fused scores + rel-shift pos + softmax + AV) -----
// One block per (i, h, b). score(j) = scale * q . (k_j + pe_{j + SEQ-1 - i}),
// valid j in [0, i + MEM + LMEM], which exactly matches the causal mask and the
// zero region of rel_shift.
__global__ __launch_bounds__(256) void attn_k(
    const float* __restrict__ Q, const float* __restrict__ KV,
    const float* __restrict__ PE, float* __restrict__ O)
{
    const int i = blockIdx.x, h = blockIdx.y, b = blockIdx.z;
    const int tid = threadIdx.x;
    const float scale = 0.08838834764831845f;   // DH^-0.5
    __shared__ float qs[128];
    __shared__ float tile[32 * 132];
    __shared__ float sc[2336];
    __shared__ float red[8];

    const float* qp = Q + ((size_t)(b * SEQ + i)) * DIM + h * DH;
    if (tid < 128) qs[tid] = qp[tid];
    const int L = i + MEMN + LMEMN + 1;         // i + 1281
    const int nT = (L + 31) >> 5;
    const float* kvb = KV + (size_t)b * KVL * (2 * DIM);
    const float* peh = PE + (size_t)h * KVL * DH;
    const int c = tid & 127;
    const int r0 = tid >> 7;
    __syncthreads();

    // Phase A: scores
    for (int t0 = 0; t0 < nT; t0++) {
        const int j0 = t0 * 32;
#pragma unroll
        for (int p = 0; p < 16; p++) {
            const int r = r0 + p * 2;
            const int j = j0 + r;
            float v = 0.f;
            if (j < L)
                v = kvb[(size_t)j * (2 * DIM) + h * DH + c] +
                    peh[(size_t)(j + SEQ - 1 - i) * DH + c];
            tile[r * 132 + c] = v;
        }
        __syncthreads();
        {
            const int jl = tid >> 3;
            const int ds = (tid & 7) * 16;
            float part = 0.f;
#pragma unroll
            for (int k = 0; k < 16; k++) part += qs[ds + k] * tile[jl * 132 + ds + k];
            part += __shfl_down_sync(0xffffffffu, part, 4, 8);
            part += __shfl_down_sync(0xffffffffu, part, 2, 8);
            part += __shfl_down_sync(0xffffffffu, part, 1, 8);
            if ((tid & 7) == 0) {
                const int j = j0 + jl;
                if (j < L) sc[j] = part * scale;
            }
        }
        __syncthreads();
    }

    // Phase B: softmax over [0, L)
    float m = -3.4e38f;
    for (int j = tid; j < L; j += 256) m = fmaxf(m, sc[j]);
#pragma unroll
    for (int off = 16; off; off >>= 1) m = fmaxf(m, __shfl_xor_sync(0xffffffffu, m, off));
    if ((tid & 31) == 0) red[tid >> 5] = m;
    __syncthreads();
    if (tid == 0) {
        float t = red[0];
#pragma unroll
        for (int r = 1; r < 8; r++) t = fmaxf(t, red[r]);
        red[0] = t;
    }
    __syncthreads();
    m = red[0];
    __syncthreads();
    float s = 0.f;
    for (int j = tid; j < L; j += 256) {
        const float e = expf(sc[j] - m);
        sc[j] = e;
        s += e;
    }
#pragma unroll
    for (int off = 16; off; off >>= 1) s += __shfl_xor_sync(0xffffffffu, s, off);
    if ((tid & 31) == 0) red[tid >> 5] = s;
    __syncthreads();
    if (tid == 0) {
        float t = 0.f;
#pragma unroll
        for (int r = 0; r < 8; r++) t += red[r];
        red[0] = 1.f / t;
    }
    __syncthreads();
    const float inv = red[0];
    for (int j = tid; j < L; j += 256) sc[j] *= inv;
    for (int j = L + tid; j < nT * 32; j += 256) sc[j] = 0.f;
    __syncthreads();

    // Phase C: out = attn @ V
    const int d = c;
    const int half = r0;
    float acc = 0.f;
    for (int t0 = 0; t0 < nT; t0++) {
        const int j0 = t0 * 32;
#pragma unroll
        for (int p = 0; p < 16; p++) {
            const int r = r0 + p * 2;
            const int j = j0 + r;
            tile[r * 132 + c] =
                (j < KVL) ? kvb[(size_t)j * (2 * DIM) + DIM + h * DH + c] : 0.f;
        }
        __syncthreads();
#pragma unroll
        for (int k = 0; k < 16; k++) {
            const int jl = half * 16 + k;
            acc += sc[j0 + jl] * tile[jl * 132 + d];
        }
        __syncthreads();
    }
    if (half == 1) qs[d] = acc;
    __syncthreads();
    if (half == 0)
        O[((size_t)(b * SEQ + i)) * DIM + h * DH + d] = acc + qs[d];
}

// ---------------- memnet: q softmax over DH per head (scale BEFORE softmax) -------
__global__ __launch_bounds__(256) void qsoftmax_k(float* __restrict__ Q)
{
    const float S = 0.29730177875068026f;       // DH^-0.25
    const int row = blockIdx.x;
    const int h = threadIdx.x >> 5;
    const int lane = threadIdx.x & 31;
    float* p = Q + (size_t)row * DIM + h * DH;
    float v0 = p[lane] * S, v1 = p[lane + 32] * S,
          v2 = p[lane + 64] * S, v3 = p[lane + 96] * S;
    float m = fmaxf(fmaxf(v0, v1), fmaxf(v2, v3));
#pragma unroll
    for (int off = 16; off; off >>= 1) m = fmaxf(m, __shfl_xor_sync(0xffffffffu, m, off));
    const float e0 = expf(v0 - m), e1 = expf(v1 - m),
                e2 = expf(v2 - m), e3 = expf(v3 - m);
    float s = e0 + e1 + e2 + e3;
#pragma unroll
    for (int off = 16; off; off >>= 1) s += __shfl_xor_sync(0xffffffffu, s, off);
    const float inv = 1.f / s;
    p[lane] = e0 * inv; p[lane + 32] = e1 * inv;
    p[lane + 64] = e2 * inv; p[lane + 96] = e3 * inv;
}

// ---------------- memnet: column-softmax stats for k (max and 1/sumexp per col) ---
__global__ __launch_bounds__(256) void kcolstat_k(const float* __restrict__ KV,
                                                  float* __restrict__ KM,
                                                  float* __restrict__ KI)
{
    const int mb = blockIdx.y;
    const int cx = threadIdx.x & 31;
    const int c = blockIdx.x * 32 + cx;
    const int ry = threadIdx.x >> 5;
    const float S = 0.29730177875068026f;
    const float* base = KV + (size_t)mb * KVL * (2 * DIM) + c;
    __shared__ float red[8][32];
    float m = -3.4e38f;
    for (int n = ry; n < KVL; n += 8) m = fmaxf(m, base[(size_t)n * (2 * DIM)]);
    red[ry][cx] = m;
    __syncthreads();
    if (ry == 0) {
#pragma unroll
        for (int r = 1; r < 8; r++) m = fmaxf(m, red[r][cx]);
        red[0][cx] = m;
    }
    __syncthreads();
    m = red[0][cx] * S;      // already scaled
    float s = 0.f;
    for (int n = ry; n < KVL; n += 8)
        s += expf(base[(size_t)n * (2 * DIM)] * S - m);
    __syncthreads();
    red[ry][cx] = s;
    __syncthreads();
    if (ry == 0) {
#pragma unroll
        for (int r = 1; r < 8; r++) s += red[r][cx];
        KM[mb * DIM + c] = m;
        KI[mb * DIM + c] = 1.f / s;
    }
}

// ---------------- memnet: ctx[d][e] = sum_n softmax(k)[n,d] * v[n,e] --------------
// One block per (mb,h), full n-range (deterministic, no atomics).
__global__ __launch_bounds__(256) void ctx_k(const float* __restrict__ KV,
                                             const float* __restrict__ KM,
                                             const float* __restrict__ KI,
                                             float* __restrict__ CTX)
{
    const int z = blockIdx.x;
    const int mb = z >> 3, h = z & 7;
    const float S = 0.29730177875068026f;
    __shared__ float ks[16][132];
    __shared__ float vs[16][132];
    const int tid = threadIdx.x;
    const int tx = tid & 15, ty = tid >> 4;
    const int c = tid & 127, r0 = tid >> 7;
    float acc[8][8];
#pragma unroll
    for (int a = 0; a < 8; a++)
#pragma unroll
        for (int b = 0; b < 8; b++) acc[a][b] = 0.f;

    const float* kvb = KV + (size_t)mb * KVL * (2 * DIM) + h * DH;
    const float kmc = KM[mb * DIM + h * DH + c];
    const float kic = KI[mb * DIM + h * DH + c];

    for (int n0 = 0; n0 < KVL; n0 += 16) {
#pragma unroll
        for (int p = 0; p < 8; p++) {
            const int r = r0 + p * 2;
            const size_t off = (size_t)(n0 + r) * (2 * DIM) + c;
            ks[r][c] = expf(kvb[off] * S - kmc) * kic;
            vs[r][c] = kvb[off + DIM];
        }
        __syncthreads();
#pragma unroll
        for (int kk = 0; kk < 16; kk++) {
            float ra[8], rb[8];
#pragma unroll
            for (int a = 0; a < 8; a++) ra[a] = ks[kk][ty * 8 + a];
#pragma unroll
            for (int b = 0; b < 8; b++) rb[b] = vs[kk][tx * 8 + b];
#pragma unroll
            for (int a = 0; a < 8; a++)
#pragma unroll
                for (int b = 0; b < 8; b++) acc[a][b] += ra[a] * rb[b];
        }
        __syncthreads();
    }
    float* ctx = CTX + (size_t)z * DH * DH;
#pragma unroll
    for (int a = 0; a < 8; a++)
#pragma unroll
        for (int b = 0; b < 8; b++)
            ctx[(ty * 8 + a) * DH + tx * 8 + b] = acc[a][b];
}

// ---------------- memnet: out[n][e] = sum_d q[n,d]*ctx[d,e]  (head-major output) --
__global__ __launch_bounds__(128) void memout_k(const float* __restrict__ Q,
                                                const float* __restrict__ CTX,
                                                float* __restrict__ O)
{
    const int z = blockIdx.x;
    const int mb = z >> 3, h = z & 7;
    const int n0 = blockIdx.y * 64;
    const int e = threadIdx.x;
    __shared__ float qs[128];
    const float* ctx = CTX + (size_t)z * DH * DH;
    for (int n = n0; n < n0 + 64; n++) {
        const size_t base = (size_t)(mb * LMEMN + n) * DIM + h * DH;
        qs[e] = Q[base + e];
        __syncthreads();
        float acc = 0.f;
#pragma unroll 16
        for (int d = 0; d < 128; d++) acc += qs[d] * ctx[d * DH + e];
        O[base + e] = acc;
        __syncthreads();
    }
}

// =================================================================================
extern "C" void kernel_launch(void* const* d_in, const int* in_sizes, int n_in,
                              void* d_out, int out_size)
{
    (void)in_sizes; (void)n_in; (void)out_size;
    const int*   x    = (const int*)  d_in[0];
    const float* mem  = (const float*)d_in[1];
    const float* lmem = (const float*)d_in[2];
    const float* temb = (const float*)d_in[3];
    const float* pemb = (const float*)d_in[4];
    const float* alng = (const float*)d_in[5];
    const float* alnb = (const float*)d_in[6];
    const float* wq   = (const float*)d_in[7];
    const float* wkv  = (const float*)d_in[8];
    const float* wo   = (const float*)d_in[9];
    const float* bo   = (const float*)d_in[10];
    const float* flng = (const float*)d_in[11];
    const float* flnb = (const float*)d_in[12];
    const float* w1   = (const float*)d_in[13];
    const float* b1   = (const float*)d_in[14];
    const float* w2   = (const float*)d_in[15];
    const float* b2   = (const float*)d_in[16];
    const float* lw   = (const float*)d_in[17];
    const float* lb   = (const float*)d_in[18];
    const float* mwq  = (const float*)d_in[19];
    const float* mwkv = (const float*)d_in[20];
    const float* mwo  = (const float*)d_in[21];
    const float* rez  = (const float*)d_in[22];

    float* out        = (float*)d_out;
    float* out_logits = out;
    float* out_nmem   = out + (size_t)BB * SEQ * VOCAB;
    float* out_nlmem  = out_nmem + (size_t)DEPTH * BB * MEMN * DIM;

    float *ph, *pn, *pq, *pkvin, *pkv, *ptmp, *pff, *pkm, *pki, *pctx;
    cudaGetSymbolAddress((void**)&ph,    g_h);
    cudaGetSymbolAddress((void**)&pn,    g_norm);
    cudaGetSymbolAddress((void**)&pq,    g_q);
    cudaGetSymbolAddress((void**)&pkvin, g_kvin);
    cudaGetSymbolAddress((void**)&pkv,   g_kv);
    cudaGetSymbolAddress((void**)&ptmp,  g_tmp);
    cudaGetSymbolAddress((void**)&pff,   g_ffmid);
    cudaGetSymbolAddress((void**)&pkm,   g_km);
    cudaGetSymbolAddress((void**)&pki,   g_ki);
    cudaGetSymbolAddress((void**)&pctx,  g_ctx);

    const int M = BB * SEQ;               // 2048

    // h = token_emb[x]
    embed_k<<<M, 256>>>(x, temb, ph);

    for (int i = 0; i < DEPTH; i++) {
        // hiddens[i] = h  (== next_mem[i], since MEM == SEQ)
        cudaMemcpyAsync(out_nmem + (size_t)i * BB * MEMN * DIM, ph,
                        sizeof(float) * (size_t)M * DIM, cudaMemcpyDeviceToDevice);
        // a_in = LN(h)
        ln_k<<<M, 256>>>(ph, alng + (size_t)i * DIM, alnb + (size_t)i * DIM, pn);
        // Q = a_in @ wq
        sgemm_k<false,false,false,false><<<dim3(DIM/128, M/128), 256>>>(
            pn, wq + (size_t)i * DIM * DIM, nullptr, nullptr, pq, M, DIM, DIM, nullptr);
        // kv_in = [lmem[i] | mem[i] | a_in]
        for (int b = 0; b < BB; b++) {
            float* dst = pkvin + (size_t)b * KVL * DIM;
            cudaMemcpyAsync(dst, lmem + ((size_t)i * BB + b) * LMEMN * DIM,
                            sizeof(float) * LMEMN * DIM, cudaMemcpyDeviceToDevice);
            cudaMemcpyAsync(dst + (size_t)LMEMN * DIM,
                            mem + ((size_t)i * BB + b) * MEMN * DIM,
                            sizeof(float) * MEMN * DIM, cudaMemcpyDeviceToDevice);
            cudaMemcpyAsync(dst + (size_t)(LMEMN + MEMN) * DIM,
                            pn + (size_t)b * SEQ * DIM,
                            sizeof(float) * SEQ * DIM, cudaMemcpyDeviceToDevice);
        }
        // KV = kv_in @ wkv
        sgemm_k<false,false,false,false><<<dim3(2*DIM/128, BB*KVL/128), 256>>>(
            pkvin, wkv + (size_t)i * DIM * 2 * DIM, nullptr, nullptr, pkv,
            BB * KVL, 2 * DIM, DIM, nullptr);
        // attention
        attn_k<<<dim3(SEQ, HEADS, BB), 256>>>(pq, pkv, pemb, ptmp);
        // h = h + attn_out @ wo + bo
        sgemm_k<true,true,false,false><<<dim3(DIM/128, M/128), 256>>>(
            ptmp, wo + (size_t)i * DIM * DIM, bo + (size_t)i * DIM, ph, ph,
            M, DIM, DIM, nullptr);
        // f_in = LN(h)
        ln_k<<<M, 256>>>(ph, flng + (size_t)i * DIM, flnb + (size_t)i * DIM, pn);
        // mid = gelu(f_in @ w1 + b1)
        sgemm_k<true,false,true,false><<<dim3(FFD/128, M/128), 256>>>(
            pn, w1 + (size_t)i * DIM * FFD, b1 + (size_t)i * FFD, nullptr, pff,
            M, FFD, DIM, nullptr);
        // h = h + mid @ w2 + b2
        sgemm_k<true,true,false,false><<<dim3(DIM/128, M/128), 256>>>(
            pff, w2 + (size_t)i * FFD * DIM, b2 + (size_t)i * DIM, ph, ph,
            M, DIM, FFD, nullptr);
    }

    // logits = h @ logits_w + logits_b
    sgemm_k<true,false,false,false><<<dim3(VOCAB/128, M/128), 256>>>(
        ph, lw, lb, nullptr, out_logits, M, VOCAB, DIM, nullptr);

    // ---------------- memory network ----------------
    const int MR = DEPTH * BB * LMEMN;    // 2048 rows of lmem
    // nl = LN(lmem)  (no affine)
    ln_k<<<MR, 256>>>(lmem, nullptr, nullptr, pn);
    // q = nl @ mem_wq, then per-head softmax over DH (scaled first)
    sgemm_k<false,false,false,false><<<dim3(DIM/128, MR/128), 256>>>(
        pn, mwq, nullptr, nullptr, pq, MR, DIM, DIM, nullptr);
    qsoftmax_k<<<MR, 256>>>(pq);
    // kv_in = [nl | mem | hiddens]  per (m,b)
    for (int i = 0; i < DEPTH; i++)
        for (int b = 0; b < BB; b++) {
            const int mb = i * BB + b;
            float* dst = pkvin + (size_t)mb * KVL * DIM;
            cudaMemcpyAsync(dst, pn + (size_t)mb * LMEMN * DIM,
                            sizeof(float) * LMEMN * DIM, cudaMemcpyDeviceToDevice);
            cudaMemcpyAsync(dst + (size_t)LMEMN * DIM,
                            mem + (size_t)mb * MEMN * DIM,
                            sizeof(float) * MEMN * DIM, cudaMemcpyDeviceToDevice);
            cudaMemcpyAsync(dst + (size_t)(LMEMN + MEMN) * DIM,
                            out_nmem + (size_t)mb * MEMN * DIM,
                            sizeof(float) * MEMN * DIM, cudaMemcpyDeviceToDevice);
        }
    // KV = kv_in @ mem_wkv
    sgemm_k<false,false,false,false><<<dim3(2*DIM/128, DEPTH*BB*KVL/128), 256>>>(
        pkvin, mwkv, nullptr, nullptr, pkv, DEPTH * BB * KVL, 2 * DIM, DIM, nullptr);
    // column softmax stats for k, then ctx = softk^T v, out = q @ ctx
    kcolstat_k<<<dim3(DIM/32, DEPTH*BB), 256>>>(pkv, pkm, pki);
    ctx_k<<<DEPTH*BB*HEADS, 256>>>(pkv, pkm, pki, pctx);
    memout_k<<<dim3(DEPTH*BB*HEADS, LMEMN/64), 128>>>(pq, pctx, ptmp);
    // next_lmem = out @ mem_wo * rezero + lmem
    sgemm_k<false,true,false,true><<<dim3(DIM/128, MR/128), 256>>>(
        ptmp, mwo, nullptr, lmem, out_nlmem, MR, DIM, DIM, rez);
}

// round 9
// speedup vs baseline: 2.5355x; 2.5355x over previous
#include <cuda_runtime.h>
#include <math.h>

#define BB     2
#define SEQ    1024
#define DIM    1024
#define HEADS  8
#define DH     128
#define MEMN   1024
#define LMEMN  256
#define KVL    2304          // LMEM + MEM + SEQ
#define DEPTH  4
#define VOCAB  32000
#define FFD    4096

// ---------------- scratch (allocation-free: __device__ globals) ----------------
__device__ float g_h[BB*SEQ*DIM];                  // residual stream        (8 MB)
__device__ float g_norm[BB*SEQ*DIM];               // LN output / memnet nl  (8 MB)
__device__ float g_q[BB*SEQ*DIM];                  // Q / memnet q           (8 MB)
__device__ float g_kvin[DEPTH*BB*KVL*DIM];         // kv_in                  (75.5 MB)
__device__ float g_kv[DEPTH*BB*KVL*2*DIM];         // kv = kv_in @ wkv       (151 MB)
__device__ float g_tmp[BB*SEQ*DIM];                // attn out / memnet out  (8 MB)
__device__ float g_ffmid[BB*SEQ*FFD];              // FF hidden              (33.5 MB)
__device__ float g_km[DEPTH*BB*DIM];               // memnet k col max*S
__device__ float g_ki[DEPTH*BB*DIM];               // memnet k col 1/sumexp
__device__ float g_ctx[DEPTH*BB*HEADS*DH*DH];      // memnet ctx             (4 MB)
__device__ float g_qk[BB*HEADS*SEQ*KVL];           // QK scores / attn       (151 MB)
__device__ float g_qp[BB*HEADS*SEQ*KVL];           // Q @ PE^T               (151 MB)

// ---------------- embedding ----------------
__global__ void embed_k(const int* __restrict__ X, const float* __restrict__ E,
                        float* __restrict__ H)
{
    const int row = blockIdx.x;
    const int tok = X[row];
    const float4* src = (const float4*)(E + (size_t)tok * DIM);
    float4* dst = (float4*)(H + (size_t)row * DIM);
    dst[threadIdx.x] = src[threadIdx.x];
}

// ---------------- LayerNorm over last dim (1024), optional affine ----------------
__global__ __launch_bounds__(256) void ln_k(const float* __restrict__ X,
                                            const float* __restrict__ G,
                                            const float* __restrict__ Bp,
                                            float* __restrict__ Y)
{
    const int tid = threadIdx.x;
    const float4 v = ((const float4*)(X + (size_t)blockIdx.x * DIM))[tid];
    __shared__ float red[8];
    float s = v.x + v.y + v.z + v.w;
#pragma unroll
    for (int off = 16; off; off >>= 1) s += __shfl_xor_sync(0xffffffffu, s, off);
    if ((tid & 31) == 0) red[tid >> 5] = s;
    __syncthreads();
    if (tid == 0) {
        float t = 0.f;
#pragma unroll
        for (int r = 0; r < 8; r++) t += red[r];
        red[0] = t * (1.f / DIM);
    }
    __syncthreads();
    const float mu = red[0];
    __syncthreads();
    const float dx = v.x - mu, dy = v.y - mu, dz = v.z - mu, dw = v.w - mu;
    float ss = dx*dx + dy*dy + dz*dz + dw*dw;
#pragma unroll
    for (int off = 16; off; off >>= 1) ss += __shfl_xor_sync(0xffffffffu, ss, off);
    if ((tid & 31) == 0) red[tid >> 5] = ss;
    __syncthreads();
    if (tid == 0) {
        float t = 0.f;
#pragma unroll
        for (int r = 0; r < 8; r++) t += red[r];
        red[0] = rsqrtf(t * (1.f / DIM) + 1e-5f);
    }
    __syncthreads();
    const float rstd = red[0];
    float4 o;
    o.x = dx * rstd; o.y = dy * rstd; o.z = dz * rstd; o.w = dw * rstd;
    if (G != nullptr) {
        const float4 g4 = ((const float4*)G)[tid];
        const float4 b4 = ((const float4*)Bp)[tid];
        o.x = o.x * g4.x + b4.x;
        o.y = o.y * g4.y + b4.y;
        o.z = o.z * g4.z + b4.z;
        o.w = o.w * g4.w + b4.w;
    }
    ((float4*)(Y + (size_t)blockIdx.x * DIM))[tid] = o;
}

// ---------------- generic SGEMM (double-buffered): C = act(A@B*alpha+bias)+res ----
// 128x128 block tile, BK=8, 8x8 per thread, 256 threads, 2-stage SMEM.
// Requires M%128==0, N%128==0, K%8==0.
template<bool BIAS, bool RES, bool GELU_ACT, bool ALPHA>
__global__ __launch_bounds__(256, 2) void sgemm_k(
    const float* __restrict__ A, const float* __restrict__ Bm,
    const float* __restrict__ bias, const float* __restrict__ R,
    float* __restrict__ C, int M, int N, int K,
    const float* __restrict__ alphaPtr)
{
    __shared__ float As[2][8][128];
    __shared__ float Bs[2][8][128];
    const int tid = threadIdx.x;
    const int aRow = tid >> 1, aCol = (tid & 1) * 4;
    const int bRow = tid >> 5, bCol = (tid & 31) * 4;
    const int tx = tid & 15, ty = tid >> 4;
    const float* Aptr = A + (size_t)blockIdx.y * 128 * K + (size_t)aRow * K + aCol;
    const float* Bptr = Bm + (size_t)blockIdx.x * 128 + (size_t)bRow * N + bCol;
    float acc[8][8];
#pragma unroll
    for (int a = 0; a < 8; a++)
#pragma unroll
        for (int b = 0; b < 8; b++) acc[a][b] = 0.f;

    float4 a4 = *(const float4*)(Aptr);
    float4 b4 = *(const float4*)(Bptr);
    As[0][aCol + 0][aRow] = a4.x; As[0][aCol + 1][aRow] = a4.y;
    As[0][aCol + 2][aRow] = a4.z; As[0][aCol + 3][aRow] = a4.w;
    *(float4*)(&Bs[0][bRow][bCol]) = b4;
    __syncthreads();

    int buf = 0;
    for (int k0 = 0; k0 < K; k0 += 8) {
        const bool more = (k0 + 8 < K);
        if (more) {
            a4 = *(const float4*)(Aptr + k0 + 8);
            b4 = *(const float4*)(Bptr + (size_t)(k0 + 8) * N);
        }
#pragma unroll
        for (int kk = 0; kk < 8; kk++) {
            float ra[8], rb[8];
#pragma unroll
            for (int a = 0; a < 8; a++) ra[a] = As[buf][kk][ty * 8 + a];
#pragma unroll
            for (int b = 0; b < 8; b++) rb[b] = Bs[buf][kk][tx * 8 + b];
#pragma unroll
            for (int a = 0; a < 8; a++)
#pragma unroll
                for (int b = 0; b < 8; b++) acc[a][b] += ra[a] * rb[b];
        }
        if (more) {
            As[buf ^ 1][aCol + 0][aRow] = a4.x; As[buf ^ 1][aCol + 1][aRow] = a4.y;
            As[buf ^ 1][aCol + 2][aRow] = a4.z; As[buf ^ 1][aCol + 3][aRow] = a4.w;
            *(float4*)(&Bs[buf ^ 1][bRow][bCol]) = b4;
            __syncthreads();
            buf ^= 1;
        }
    }

    float alpha = 1.f;
    if (ALPHA) alpha = *alphaPtr;
    const int colBase = blockIdx.x * 128 + tx * 8;
    const size_t rowBase = (size_t)blockIdx.y * 128 + ty * 8;
#pragma unroll
    for (int a = 0; a < 8; a++) {
        const size_t off = (rowBase + a) * (size_t)N + colBase;
#pragma unroll
        for (int b = 0; b < 8; b++) {
            float v = acc[a][b];
            if (ALPHA) v *= alpha;
            if (BIAS) v += bias[colBase + b];
            if (GELU_ACT) v = 0.5f * v * (1.f + erff(v * 0.70710678118654752440f));
            if (RES) v += R[off + b];
            C[off + b] = v;
        }
    }
}

// ---------------- batched NT GEMM: C = A @ B^T (per z = b*8+h) --------------------
// A: M x K rows at lda; B: N x K rows at ldb; C: M x N at ldc. 128x128 tiles.
__global__ __launch_bounds__(256, 2) void bgemm_nt_k(
    const float* __restrict__ A, const float* __restrict__ B, float* __restrict__ C,
    int lda, int ldb, int ldc,
    long sAb, long sAh, long sBb, long sBh, long sCb, long sCh, int K)
{
    const int bb = blockIdx.z >> 3, hh = blockIdx.z & 7;
    A += bb * sAb + hh * sAh;
    B += bb * sBb + hh * sBh;
    C += bb * sCb + hh * sCh;

    __shared__ float As[2][8][128];
    __shared__ float Bs[2][8][128];
    const int tid = threadIdx.x;
    const int lRow = tid >> 1, lCol = (tid & 1) * 4;   // same mapping for A and B
    const int tx = tid & 15, ty = tid >> 4;
    const float* Aptr = A + (size_t)(blockIdx.y * 128 + lRow) * lda + lCol;
    const float* Bptr = B + (size_t)(blockIdx.x * 128 + lRow) * ldb + lCol;
    float acc[8][8];
#pragma unroll
    for (int a = 0; a < 8; a++)
#pragma unroll
        for (int b = 0; b < 8; b++) acc[a][b] = 0.f;

    float4 a4 = *(const float4*)(Aptr);
    float4 b4 = *(const float4*)(Bptr);
    As[0][lCol + 0][lRow] = a4.x; As[0][lCol + 1][lRow] = a4.y;
    As[0][lCol + 2][lRow] = a4.z; As[0][lCol + 3][lRow] = a4.w;
    Bs[0][lCol + 0][lRow] = b4.x; Bs[0][lCol + 1][lRow] = b4.y;
    Bs[0][lCol + 2][lRow] = b4.z; Bs[0][lCol + 3][lRow] = b4.w;
    __syncthreads();

    int buf = 0;
    for (int k0 = 0; k0 < K; k0 += 8) {
        const bool more = (k0 + 8 < K);
        if (more) {
            a4 = *(const float4*)(Aptr + k0 + 8);
            b4 = *(const float4*)(Bptr + k0 + 8);
        }
#pragma unroll
        for (int kk = 0; kk < 8; kk++) {
            float ra[8], rb[8];
#pragma unroll
            for (int a = 0; a < 8; a++) ra[a] = As[buf][kk][ty * 8 + a];
#pragma unroll
            for (int b = 0; b < 8; b++) rb[b] = Bs[buf][kk][tx * 8 + b];
#pragma unroll
            for (int a = 0; a < 8; a++)
#pragma unroll
                for (int b = 0; b < 8; b++) acc[a][b] += ra[a] * rb[b];
        }
        if (more) {
            As[buf ^ 1][lCol + 0][lRow] = a4.x; As[buf ^ 1][lCol + 1][lRow] = a4.y;
            As[buf ^ 1][lCol + 2][lRow] = a4.z; As[buf ^ 1][lCol + 3][lRow] = a4.w;
            Bs[buf ^ 1][lCol + 0][lRow] = b4.x; Bs[buf ^ 1][lCol + 1][lRow] = b4.y;
            Bs[buf ^ 1][lCol + 2][lRow] = b4.z; Bs[buf ^ 1][lCol + 3][lRow] = b4.w;
            __syncthreads();
            buf ^= 1;
        }
    }
    const int colBase = blockIdx.x * 128 + tx * 8;
    const size_t rowBase = (size_t)blockIdx.y * 128 + ty * 8;
#pragma unroll
    for (int a = 0; a < 8; a++) {
        float* crow = C + (rowBase + a) * (size_t)ldc + colBase;
#pragma unroll
        for (int b = 0; b < 8; b++) crow[b] = acc[a][b];
    }
}

// ---------------- batched NN GEMM: C = A @ B (per z = b*8+h) ----------------------
__global__ __launch_bounds__(256, 2) void bgemm_nn_k(
    const float* __restrict__ A, const float* __restrict__ B, float* __restrict__ C,
    int lda, int ldb, int ldc,
    long sAb, long sAh, long sBb, long sBh, long sCb, long sCh, int K)
{
    const int bb = blockIdx.z >> 3, hh = blockIdx.z & 7;
    A += bb * sAb + hh * sAh;
    B += bb * sBb + hh * sBh;
    C += bb * sCb + hh * sCh;

    __shared__ float As[2][8][128];
    __shared__ float Bs[2][8][128];
    const int tid = threadIdx.x;
    const int aRow = tid >> 1, aCol = (tid & 1) * 4;
    const int bRow = tid >> 5, bCol = (tid & 31) * 4;
    const int tx = tid & 15, ty = tid >> 4;
    const float* Aptr = A + (size_t)(blockIdx.y * 128 + aRow) * lda + aCol;
    const float* Bptr = B + (size_t)blockIdx.x * 128 + (size_t)bRow * ldb + bCol;
    float acc[8][8];
#pragma unroll
    for (int a = 0; a < 8; a++)
#pragma unroll
        for (int b = 0; b < 8; b++) acc[a][b] = 0.f;

    float4 a4 = *(const float4*)(Aptr);
    float4 b4 = *(const float4*)(Bptr);
    As[0][aCol + 0][aRow] = a4.x; As[0][aCol + 1][aRow] = a4.y;
    As[0][aCol + 2][aRow] = a4.z; As[0][aCol + 3][aRow] = a4.w;
    *(float4*)(&Bs[0][bRow][bCol]) = b4;
    __syncthreads();

    int buf = 0;
    for (int k0 = 0; k0 < K; k0 += 8) {
        const bool more = (k0 + 8 < K);
        if (more) {
            a4 = *(const float4*)(Aptr + k0 + 8);
            b4 = *(const float4*)(Bptr + (size_t)(k0 + 8) * ldb);
        }
#pragma unroll
        for (int kk = 0; kk < 8; kk++) {
            float ra[8], rb[8];
#pragma unroll
            for (int a = 0; a < 8; a++) ra[a] = As[buf][kk][ty * 8 + a];
#pragma unroll
            for (int b = 0; b < 8; b++) rb[b] = Bs[buf][kk][tx * 8 + b];
#pragma unroll
            for (int a = 0; a < 8; a++)
#pragma unroll
                for (int b = 0; b < 8; b++) acc[a][b] += ra[a] * rb[b];
        }
        if (more) {
            As[buf ^ 1][aCol + 0][aRow] = a4.x; As[buf ^ 1][aCol + 1][aRow] = a4.y;
            As[buf ^ 1][aCol + 2][aRow] = a4.z; As[buf ^ 1][aCol + 3][aRow] = a4.w;
            *(float4*)(&Bs[buf ^ 1][bRow][bCol]) = b4;
            __syncthreads();
            buf ^= 1;
        }
    }
    const int colBase = blockIdx.x * 128 + tx * 8;
    const size_t rowBase = (size_t)blockIdx.y * 128 + ty * 8;
#pragma unroll
    for (int a = 0; a < 8; a++) {
        float* crow = C + (rowBase + a) * (size_t)ldc + colBase;
#pragma unroll
        for (int b = 0; b < 8; b++) crow[b] = acc[a][b];
    }
}

// ---------------- rel-shift + mask + softmax (in-place over QK) -------------------
// One block per (i, z). attn[j] = softmax_j( scale*(QK[j] + QP[j+SEQ-1-i]) ), j<L;
// zeros for j in [L, KVL) so the AV GEMM over full KVL is exact.
__global__ __launch_bounds__(256) void softmax_rel_k(float* __restrict__ QK,
                                                     const float* __restrict__ QP)
{
    const int i = blockIdx.x;
    const int z = blockIdx.y;
    const int tid = threadIdx.x;
    const float scale = 0.08838834764831845f;   // DH^-0.5
    float* row = QK + ((size_t)z * SEQ + i) * KVL;
    const float* prow = QP + ((size_t)z * SEQ + i) * KVL + (SEQ - 1 - i);
    const int L = i + MEMN + LMEMN + 1;
    __shared__ float red[8];

    float sv[9];
    float m = -3.4e38f;
#pragma unroll
    for (int t = 0; t < 9; t++) {
        const int j = tid + 256 * t;
        float v = -3.4e38f;
        if (j < L) v = scale * (row[j] + prow[j]);
        sv[t] = v;
        m = fmaxf(m, v);
    }
#pragma unroll
    for (int off = 16; off; off >>= 1) m = fmaxf(m, __shfl_xor_sync(0xffffffffu, m, off));
    if ((tid & 31) == 0) red[tid >> 5] = m;
    __syncthreads();
    if (tid == 0) {
        float t = red[0];
#pragma unroll
        for (int r = 1; r < 8; r++) t = fmaxf(t, red[r]);
        red[0] = t;
    }
    __syncthreads();
    m = red[0];
    __syncthreads();
    float s = 0.f;
#pragma unroll
    for (int t = 0; t < 9; t++) {
        const int j = tid + 256 * t;
        float e = 0.f;
        if (j < L) e = expf(sv[t] - m);
        sv[t] = e;
        s += e;
    }
#pragma unroll
    for (int off = 16; off; off >>= 1) s += __shfl_xor_sync(0xffffffffu, s, off);
    if ((tid & 31) == 0) red[tid >> 5] = s;
    __syncthreads();
    if (tid == 0) {
        float t = 0.f;
#pragma unroll
        for (int r = 0; r < 8; r++) t += red[r];
        red[0] = 1.f / t;
    }
    __syncthreads();
    const float inv = red[0];
#pragma unroll
    for (int t = 0; t < 9; t++) {
        const int j = tid + 256 * t;
        row[j] = sv[t] * inv;       // zero beyond L (sv[t]==0 there)
    }
}

// ---------------- memnet: q softmax over DH per head (scale BEFORE softmax) -------
__global__ __launch_bounds__(256) void qsoftmax_k(float* __restrict__ Q)
{
    const float S = 0.29730177875068026f;       // DH^-0.25
    const int row = blockIdx.x;
    const int h = threadIdx.x >> 5;
    const int lane = threadIdx.x & 31;
    float* p = Q + (size_t)row * DIM + h * DH;
    float v0 = p[lane] * S, v1 = p[lane + 32] * S,
          v2 = p[lane + 64] * S, v3 = p[lane + 96] * S;
    float m = fmaxf(fmaxf(v0, v1), fmaxf(v2, v3));
#pragma unroll
    for (int off = 16; off; off >>= 1) m = fmaxf(m, __shfl_xor_sync(0xffffffffu, m, off));
    const float e0 = expf(v0 - m), e1 = expf(v1 - m),
                e2 = expf(v2 - m), e3 = expf(v3 - m);
    float s = e0 + e1 + e2 + e3;
#pragma unroll
    for (int off = 16; off; off >>= 1) s += __shfl_xor_sync(0xffffffffu, s, off);
    const float inv = 1.f / s;
    p[lane] = e0 * inv; p[lane + 32] = e1 * inv;
    p[lane + 64] = e2 * inv; p[lane + 96] = e3 * inv;
}

// ---------------- memnet: column-softmax stats for k (max and 1/sumexp per col) ---
__global__ __launch_bounds__(256) void kcolstat_k(const float* __restrict__ KV,
                                                  float* __restrict__ KM,
                                                  float* __restrict__ KI)
{
    const int mb = blockIdx.y;
    const int cx = threadIdx.x & 31;
    const int c = blockIdx.x * 32 + cx;
    const int ry = threadIdx.x >> 5;
    const float S = 0.29730177875068026f;
    const float* base = KV + (size_t)mb * KVL * (2 * DIM) + c;
    __shared__ float red[8][32];
    float m = -3.4e38f;
    for (int n = ry; n < KVL; n += 8) m = fmaxf(m, base[(size_t)n * (2 * DIM)]);
    red[ry][cx] = m;
    __syncthreads();
    if (ry == 0) {
#pragma unroll
        for (int r = 1; r < 8; r++) m = fmaxf(m, red[r][cx]);
        red[0][cx] = m;
    }
    __syncthreads();
    m = red[0][cx] * S;      // already scaled
    float s = 0.f;
    for (int n = ry; n < KVL; n += 8)
        s += expf(base[(size_t)n * (2 * DIM)] * S - m);
    __syncthreads();
    red[ry][cx] = s;
    __syncthreads();
    if (ry == 0) {
#pragma unroll
        for (int r = 1; r < 8; r++) s += red[r][cx];
        KM[mb * DIM + c] = m;
        KI[mb * DIM + c] = 1.f / s;
    }
}

// ---------------- memnet: ctx[d][e] = sum_n softmax(k)[n,d] * v[n,e] --------------
__global__ __launch_bounds__(256) void ctx_k(const float* __restrict__ KV,
                                             const float* __restrict__ KM,
                                             const float* __restrict__ KI,
                                             float* __restrict__ CTX)
{
    const int z = blockIdx.x;
    const int mb = z >> 3, h = z & 7;
    const float S = 0.29730177875068026f;
    __shared__ float ks[16][132];
    __shared__ float vs[16][132];
    const int tid = threadIdx.x;
    const int tx = tid & 15, ty = tid >> 4;
    const int c = tid & 127, r0 = tid >> 7;
    float acc[8][8];
#pragma unroll
    for (int a = 0; a < 8; a++)
#pragma unroll
        for (int b = 0; b < 8; b++) acc[a][b] = 0.f;

    const float* kvb = KV + (size_t)mb * KVL * (2 * DIM) + h * DH;
    const float kmc = KM[mb * DIM + h * DH + c];
    const float kic = KI[mb * DIM + h * DH + c];

    for (int n0 = 0; n0 < KVL; n0 += 16) {
#pragma unroll
        for (int p = 0; p < 8; p++) {
            const int r = r0 + p * 2;
            const size_t off = (size_t)(n0 + r) * (2 * DIM) + c;
            ks[r][c] = expf(kvb[off] * S - kmc) * kic;
            vs[r][c] = kvb[off + DIM];
        }
        __syncthreads();
#pragma unroll
        for (int kk = 0; kk < 16; kk++) {
            float ra[8], rb[8];
#pragma unroll
            for (int a = 0; a < 8; a++) ra[a] = ks[kk][ty * 8 + a];
#pragma unroll
            for (int b = 0; b < 8; b++) rb[b] = vs[kk][tx * 8 + b];
#pragma unroll
            for (int a = 0; a < 8; a++)
#pragma unroll
                for (int b = 0; b < 8; b++) acc[a][b] += ra[a] * rb[b];
        }
        __syncthreads();
    }
    float* ctx = CTX + (size_t)z * DH * DH;
#pragma unroll
    for (int a = 0; a < 8; a++)
#pragma unroll
        for (int b = 0; b < 8; b++)
            ctx[(ty * 8 + a) * DH + tx * 8 + b] = acc[a][b];
}

// ---------------- memnet: out[n][e] = sum_d q[n,d]*ctx[d,e]  (head-major output) --
__global__ __launch_bounds__(128) void memout_k(const float* __restrict__ Q,
                                                const float* __restrict__ CTX,
                                                float* __restrict__ O)
{
    const int z = blockIdx.x;
    const int mb = z >> 3, h = z & 7;
    const int n0 = blockIdx.y * 64;
    const int e = threadIdx.x;
    __shared__ float qs[128];
    const float* ctx = CTX + (size_t)z * DH * DH;
    for (int n = n0; n < n0 + 64; n++) {
        const size_t base = (size_t)(mb * LMEMN + n) * DIM + h * DH;
        qs[e] = Q[base + e];
        __syncthreads();
        float acc = 0.f;
#pragma unroll 16
        for (int d = 0; d < 128; d++) acc += qs[d] * ctx[d * DH + e];
        O[base + e] = acc;
        __syncthreads();
    }
}

// =================================================================================
extern "C" void kernel_launch(void* const* d_in, const int* in_sizes, int n_in,
                              void* d_out, int out_size)
{
    (void)in_sizes; (void)n_in; (void)out_size;
    const int*   x    = (const int*)  d_in[0];
    const float* mem  = (const float*)d_in[1];
    const float* lmem = (const float*)d_in[2];
    const float* temb = (const float*)d_in[3];
    const float* pemb = (const float*)d_in[4];
    const float* alng = (const float*)d_in[5];
    const float* alnb = (const float*)d_in[6];
    const float* wq   = (const float*)d_in[7];
    const float* wkv  = (const float*)d_in[8];
    const float* wo   = (const float*)d_in[9];
    const float* bo   = (const float*)d_in[10];
    const float* flng = (const float*)d_in[11];
    const float* flnb = (const float*)d_in[12];
    const float* w1   = (const float*)d_in[13];
    const float* b1   = (const float*)d_in[14];
    const float* w2   = (const float*)d_in[15];
    const float* b2   = (const float*)d_in[16];
    const float* lw   = (const float*)d_in[17];
    const float* lb   = (const float*)d_in[18];
    const float* mwq  = (const float*)d_in[19];
    const float* mwkv = (const float*)d_in[20];
    const float* mwo  = (const float*)d_in[21];
    const float* rez  = (const float*)d_in[22];

    float* out        = (float*)d_out;
    float* out_logits = out;
    float* out_nmem   = out + (size_t)BB * SEQ * VOCAB;
    float* out_nlmem  = out_nmem + (size_t)DEPTH * BB * MEMN * DIM;

    float *ph, *pn, *pq, *pkvin, *pkv, *ptmp, *pff, *pkm, *pki, *pctx, *pqk, *pqp;
    cudaGetSymbolAddress((void**)&ph,    g_h);
    cudaGetSymbolAddress((void**)&pn,    g_norm);
    cudaGetSymbolAddress((void**)&pq,    g_q);
    cudaGetSymbolAddress((void**)&pkvin, g_kvin);
    cudaGetSymbolAddress((void**)&pkv,   g_kv);
    cudaGetSymbolAddress((void**)&ptmp,  g_tmp);
    cudaGetSymbolAddress((void**)&pff,   g_ffmid);
    cudaGetSymbolAddress((void**)&pkm,   g_km);
    cudaGetSymbolAddress((void**)&pki,   g_ki);
    cudaGetSymbolAddress((void**)&pctx,  g_ctx);
    cudaGetSymbolAddress((void**)&pqk,   g_qk);
    cudaGetSymbolAddress((void**)&pqp,   g_qp);

    const int M = BB * SEQ;               // 2048
    const long sSKV = (long)SEQ * KVL;    // per-head score stride

    // h = token_emb[x]
    embed_k<<<M, 256>>>(x, temb, ph);

    for (int i = 0; i < DEPTH; i++) {
        // hiddens[i] = h  (== next_mem[i], since MEM == SEQ)
        cudaMemcpyAsync(out_nmem + (size_t)i * BB * MEMN * DIM, ph,
                        sizeof(float) * (size_t)M * DIM, cudaMemcpyDeviceToDevice);
        // a_in = LN(h)
        ln_k<<<M, 256>>>(ph, alng + (size_t)i * DIM, alnb + (size_t)i * DIM, pn);
        // Q = a_in @ wq
        sgemm_k<false,false,false,false><<<dim3(DIM/128, M/128), 256>>>(
            pn, wq + (size_t)i * DIM * DIM, nullptr, nullptr, pq, M, DIM, DIM, nullptr);
        // kv_in = [lmem[i] | mem[i] | a_in]
        for (int b = 0; b < BB; b++) {
            float* dst = pkvin + (size_t)b * KVL * DIM;
            cudaMemcpyAsync(dst, lmem + ((size_t)i * BB + b) * LMEMN * DIM,
                            sizeof(float) * LMEMN * DIM, cudaMemcpyDeviceToDevice);
            cudaMemcpyAsync(dst + (size_t)LMEMN * DIM,
                            mem + ((size_t)i * BB + b) * MEMN * DIM,
                            sizeof(float) * MEMN * DIM, cudaMemcpyDeviceToDevice);
            cudaMemcpyAsync(dst + (size_t)(LMEMN + MEMN) * DIM,
                            pn + (size_t)b * SEQ * DIM,
                            sizeof(float) * SEQ * DIM, cudaMemcpyDeviceToDevice);
        }
        // KV = kv_in @ wkv
        sgemm_k<false,false,false,false><<<dim3(2*DIM/128, BB*KVL/128), 256>>>(
            pkvin, wkv + (size_t)i * DIM * 2 * DIM, nullptr, nullptr, pkv,
            BB * KVL, 2 * DIM, DIM, nullptr);
        // --- attention as batched GEMMs ---
        // QK[z] = Q[b,:,h] @ K[b,:,h]^T        (z = b*8+h)
        bgemm_nt_k<<<dim3(KVL/128, SEQ/128, BB*HEADS), 256>>>(
            pq, pkv, pqk,
            DIM, 2*DIM, KVL,
            (long)SEQ*DIM, DH,            // A strides (b,h)
            (long)KVL*2*DIM, DH,          // B strides
            (long)HEADS*sSKV, sSKV,       // C strides
            DH);
        // QP[z] = Q[b,:,h] @ PE[h]^T
        bgemm_nt_k<<<dim3(KVL/128, SEQ/128, BB*HEADS), 256>>>(
            pq, pemb, pqp,
            DIM, DH, KVL,
            (long)SEQ*DIM, DH,
            0L, (long)KVL*DH,
            (long)HEADS*sSKV, sSKV,
            DH);
        // shift + mask + softmax (in place into pqk)
        softmax_rel_k<<<dim3(SEQ, BB*HEADS), 256>>>(pqk, pqp);
        // out[b,:,h] = attn[z] @ V[b,:,h]
        bgemm_nn_k<<<dim3(DH/128, SEQ/128, BB*HEADS), 256>>>(
            pqk, pkv + DIM, ptmp,
            KVL, 2*DIM, DIM,
            (long)HEADS*sSKV, sSKV,
            (long)KVL*2*DIM, DH,
            (long)SEQ*DIM, DH,
            KVL);
        // h = h + attn_out @ wo + bo
        sgemm_k<true,true,false,false><<<dim3(DIM/128, M/128), 256>>>(
            ptmp, wo + (size_t)i * DIM * DIM, bo + (size_t)i * DIM, ph, ph,
            M, DIM, DIM, nullptr);
        // f_in = LN(h)
        ln_k<<<M, 256>>>(ph, flng + (size_t)i * DIM, flnb + (size_t)i * DIM, pn);
        // mid = gelu(f_in @ w1 + b1)
        sgemm_k<true,false,true,false><<<dim3(FFD/128, M/128), 256>>>(
            pn, w1 + (size_t)i * DIM * FFD, b1 + (size_t)i * FFD, nullptr, pff,
            M, FFD, DIM, nullptr);
        // h = h + mid @ w2 + b2
        sgemm_k<true,true,false,false><<<dim3(DIM/128, M/128), 256>>>(
            pff, w2 + (size_t)i * FFD * DIM, b2 + (size_t)i * DIM, ph, ph,
            M, DIM, FFD, nullptr);
    }

    // logits = h @ logits_w + logits_b
    sgemm_k<true,false,false,false><<<dim3(VOCAB/128, M/128), 256>>>(
        ph, lw, lb, nullptr, out_logits, M, VOCAB, DIM, nullptr);

    // ---------------- memory network ----------------
    const int MR = DEPTH * BB * LMEMN;    // 2048 rows of lmem
    // nl = LN(lmem)  (no affine)
    ln_k<<<MR, 256>>>(lmem, nullptr, nullptr, pn);
    // q = nl @ mem_wq, then per-head softmax over DH (scaled first)
    sgemm_k<false,false,false,false><<<dim3(DIM/128, MR/128), 256>>>(
        pn, mwq, nullptr, nullptr, pq, MR, DIM, DIM, nullptr);
    qsoftmax_k<<<MR, 256>>>(pq);
    // kv_in = [nl | mem | hiddens]  per (m,b)
    for (int i = 0; i < DEPTH; i++)
        for (int b = 0; b < BB; b++) {
            const int mb = i * BB + b;
            float* dst = pkvin + (size_t)mb * KVL * DIM;
            cudaMemcpyAsync(dst, pn + (size_t)mb * LMEMN * DIM,
                            sizeof(float) * LMEMN * DIM, cudaMemcpyDeviceToDevice);
            cudaMemcpyAsync(dst + (size_t)LMEMN * DIM,
                            mem + (size_t)mb * MEMN * DIM,
                            sizeof(float) * MEMN * DIM, cudaMemcpyDeviceToDevice);
            cudaMemcpyAsync(dst + (size_t)(LMEMN + MEMN) * DIM,
                            out_nmem + (size_t)mb * MEMN * DIM,
                            sizeof(float) * MEMN * DIM, cudaMemcpyDeviceToDevice);
        }
    // KV = kv_in @ mem_wkv
    sgemm_k<false,false,false,false><<<dim3(2*DIM/128, DEPTH*BB*KVL/128), 256>>>(
        pkvin, mwkv, nullptr, nullptr, pkv, DEPTH * BB * KVL, 2 * DIM, DIM, nullptr);
    // column softmax stats for k, then ctx = softk^T v, out = q @ ctx
    kcolstat_k<<<dim3(DIM/32, DEPTH*BB), 256>>>(pkv, pkm, pki);
    ctx_k<<<DEPTH*BB*HEADS, 256>>>(pkv, pkm, pki, pctx);
    memout_k<<<dim3(DEPTH*BB*HEADS, LMEMN/64), 128>>>(pq, pctx, ptmp);
    // next_lmem = out @ mem_wo * rezero + lmem
    sgemm_k<false,true,false,true><<<dim3(DIM/128, MR/128), 256>>>(
        ptmp, mwo, nullptr, lmem, out_nlmem, MR, DIM, DIM, rez);
}

// round 10
// speedup vs baseline: 3.4029x; 1.3421x over previous
#include <cuda_runtime.h>
#include <math.h>
#include <stdint.h>

#define BB     2
#define SEQ    1024
#define DIM    1024
#define HEADS  8
#define DH     128
#define MEMN   1024
#define LMEMN  256
#define KVL    2304          // LMEM + MEM + SEQ
#define DEPTH  4
#define VOCAB  32000
#define FFD    4096

// ---------------- scratch (allocation-free: __device__ globals) ----------------
__device__ float g_h[BB*SEQ*DIM];                  // residual stream        (8 MB)
__device__ float g_norm[BB*SEQ*DIM];               // LN output / memnet nl  (8 MB)
__device__ float g_q[BB*SEQ*DIM];                  // Q / memnet q           (8 MB)
__device__ float g_kvin[DEPTH*BB*KVL*DIM];         // kv_in                  (75.5 MB)
__device__ float g_kv[DEPTH*BB*KVL*2*DIM];         // kv = kv_in @ wkv       (151 MB)
__device__ float g_tmp[BB*SEQ*DIM];                // attn out / memnet out  (8 MB)
__device__ float g_ffmid[BB*SEQ*FFD];              // FF hidden              (33.5 MB)
__device__ float g_km[DEPTH*BB*DIM];               // memnet k col max*S
__device__ float g_ki[DEPTH*BB*DIM];               // memnet k col 1/sumexp
__device__ float g_ctx[DEPTH*BB*HEADS*DH*DH];      // memnet ctx             (4 MB)
__device__ float g_qk[BB*HEADS*SEQ*KVL];           // QK scores / attn       (151 MB)
__device__ float g_qp[BB*HEADS*SEQ*KVL];           // Q @ PE^T               (151 MB)

// ---------------- embedding ----------------
__global__ void embed_k(const int* __restrict__ X, const float* __restrict__ E,
                        float* __restrict__ H)
{
    const int row = blockIdx.x;
    const int tok = X[row];
    const float4* src = (const float4*)(E + (size_t)tok * DIM);
    float4* dst = (float4*)(H + (size_t)row * DIM);
    dst[threadIdx.x] = src[threadIdx.x];
}

// ---------------- LayerNorm over last dim (1024), optional affine ----------------
__global__ __launch_bounds__(256) void ln_k(const float* __restrict__ X,
                                            const float* __restrict__ G,
                                            const float* __restrict__ Bp,
                                            float* __restrict__ Y)
{
    const int tid = threadIdx.x;
    const float4 v = ((const float4*)(X + (size_t)blockIdx.x * DIM))[tid];
    __shared__ float red[8];
    float s = v.x + v.y + v.z + v.w;
#pragma unroll
    for (int off = 16; off; off >>= 1) s += __shfl_xor_sync(0xffffffffu, s, off);
    if ((tid & 31) == 0) red[tid >> 5] = s;
    __syncthreads();
    if (tid == 0) {
        float t = 0.f;
#pragma unroll
        for (int r = 0; r < 8; r++) t += red[r];
        red[0] = t * (1.f / DIM);
    }
    __syncthreads();
    const float mu = red[0];
    __syncthreads();
    const float dx = v.x - mu, dy = v.y - mu, dz = v.z - mu, dw = v.w - mu;
    float ss = dx*dx + dy*dy + dz*dz + dw*dw;
#pragma unroll
    for (int off = 16; off; off >>= 1) ss += __shfl_xor_sync(0xffffffffu, ss, off);
    if ((tid & 31) == 0) red[tid >> 5] = ss;
    __syncthreads();
    if (tid == 0) {
        float t = 0.f;
#pragma unroll
        for (int r = 0; r < 8; r++) t += red[r];
        red[0] = rsqrtf(t * (1.f / DIM) + 1e-5f);
    }
    __syncthreads();
    const float rstd = red[0];
    float4 o;
    o.x = dx * rstd; o.y = dy * rstd; o.z = dz * rstd; o.w = dw * rstd;
    if (G != nullptr) {
        const float4 g4 = ((const float4*)G)[tid];
        const float4 b4 = ((const float4*)Bp)[tid];
        o.x = o.x * g4.x + b4.x;
        o.y = o.y * g4.y + b4.y;
        o.z = o.z * g4.z + b4.z;
        o.w = o.w * g4.w + b4.w;
    }
    ((float4*)(Y + (size_t)blockIdx.x * DIM))[tid] = o;
}

// ---------------- tf32 helpers ----------------
__device__ __forceinline__ void split_tf32(float x, uint32_t& hi, uint32_t& lo)
{
    asm("cvt.rna.tf32.f32 %0, %1;" : "=r"(hi) : "f"(x));
    const float l = x - __uint_as_float(hi);
    asm("cvt.rna.tf32.f32 %0, %1;" : "=r"(lo) : "f"(l));
}

__device__ __forceinline__ void mma8(float c[4],
                                     uint32_t a0, uint32_t a1, uint32_t a2, uint32_t a3,
                                     uint32_t b0, uint32_t b1)
{
    asm volatile(
        "mma.sync.aligned.m16n8k8.row.col.f32.tf32.tf32.f32 "
        "{%0,%1,%2,%3}, {%4,%5,%6,%7}, {%8,%9}, {%0,%1,%2,%3};"
        : "+f"(c[0]), "+f"(c[1]), "+f"(c[2]), "+f"(c[3])
        : "r"(a0), "r"(a1), "r"(a2), "r"(a3), "r"(b0), "r"(b1));
}

// ---------------- unified tensor-core GEMM (3xTF32) -------------------------------
// C = act(A@op(B) * alpha + bias) + res.  A row-major MxK.
// BT=true : B is N x K row-major (NT GEMM).  BT=false: B is K x N row-major (NN).
// 128x128 block tile, BK=16, 8 warps each computing 64x32 via m16n8k8 mma.
// Requires M%128==0, N%128==0, K%16==0 (true for every call here).
// Batched over gridDim.z (z = bb*8 + hh); pass zero strides for unbatched.
template<bool BT, bool BIAS, bool RES, bool GELU_ACT, bool ALPHA>
__global__ __launch_bounds__(256, 1) void tgemm_k(
    const float* __restrict__ A, const float* __restrict__ B,
    const float* __restrict__ bias, const float* __restrict__ R,
    float* __restrict__ C,
    int lda, int ldb, int ldc, int K,
    long sAb, long sAh, long sBb, long sBh, long sCb, long sCh,
    const float* __restrict__ alphaPtr)
{
    const int bb = blockIdx.z >> 3, hh = blockIdx.z & 7;
    A += bb * sAb + hh * sAh;
    B += bb * sBb + hh * sBh;
    C += bb * sCb + hh * sCh;

    __shared__ float As[2][16][136];
    __shared__ float Bs[2][16][136];

    const int tid  = threadIdx.x;
    const int lane = tid & 31, warp = tid >> 5;
    const int g  = lane >> 2, tg = lane & 3;
    const int mW = (warp >> 2) * 64;     // warp row base (0 or 64)
    const int nW = (warp & 3) * 32;      // warp col base
    const int blockRow = blockIdx.y * 128;
    const int blockCol = blockIdx.x * 128;

    // staging assignment
    const int sM = tid >> 1;             // 0..127
    const int sK = (tid & 1) * 8;        // 0 or 8
    const float* aSrc = A + (size_t)(blockRow + sM) * lda + sK;
    const float* bSrc;
    int bK = 0, bN = 0;
    if (BT) {
        bSrc = B + (size_t)(blockCol + sM) * ldb + sK;
    } else {
        bK = tid >> 4;                   // 0..15
        bN = (tid & 15) * 8;             // 0..120
        bSrc = B + (size_t)bK * ldb + blockCol + bN;
    }

    float4 ar0, ar1, br0, br1;
    auto stash = [&](int sb) {
        As[sb][sK + 0][sM] = ar0.x; As[sb][sK + 1][sM] = ar0.y;
        As[sb][sK + 2][sM] = ar0.z; As[sb][sK + 3][sM] = ar0.w;
        As[sb][sK + 4][sM] = ar1.x; As[sb][sK + 5][sM] = ar1.y;
        As[sb][sK + 6][sM] = ar1.z; As[sb][sK + 7][sM] = ar1.w;
        if (BT) {
            Bs[sb][sK + 0][sM] = br0.x; Bs[sb][sK + 1][sM] = br0.y;
            Bs[sb][sK + 2][sM] = br0.z; Bs[sb][sK + 3][sM] = br0.w;
            Bs[sb][sK + 4][sM] = br1.x; Bs[sb][sK + 5][sM] = br1.y;
            Bs[sb][sK + 6][sM] = br1.z; Bs[sb][sK + 7][sM] = br1.w;
        } else {
            *(float4*)&Bs[sb][bK][bN]     = br0;
            *(float4*)&Bs[sb][bK][bN + 4] = br1;
        }
    };

    // stage 0
    ar0 = *(const float4*)(aSrc);
    ar1 = *(const float4*)(aSrc + 4);
    br0 = *(const float4*)(bSrc);
    br1 = *(const float4*)(bSrc + 4);
    stash(0);
    __syncthreads();

    float acc[4][4][4];
#pragma unroll
    for (int mi = 0; mi < 4; mi++)
#pragma unroll
        for (int ni = 0; ni < 4; ni++)
#pragma unroll
            for (int r = 0; r < 4; r++) acc[mi][ni][r] = 0.f;

    int buf = 0;
    for (int k0 = 0; k0 < K; k0 += 16) {
        const bool more = (k0 + 16 < K);
        if (more) {
            ar0 = *(const float4*)(aSrc + k0 + 16);
            ar1 = *(const float4*)(aSrc + k0 + 20);
            if (BT) {
                br0 = *(const float4*)(bSrc + k0 + 16);
                br1 = *(const float4*)(bSrc + k0 + 20);
            } else {
                const float* p = bSrc + (size_t)(k0 + 16) * ldb;
                br0 = *(const float4*)(p);
                br1 = *(const float4*)(p + 4);
            }
        }
#pragma unroll
        for (int k8 = 0; k8 < 16; k8 += 8) {
            uint32_t ah[4][4], al[4][4], bh[4][2], bl[4][2];
#pragma unroll
            for (int mi = 0; mi < 4; mi++) {
                const int m0 = mW + mi * 16 + g;
                split_tf32(As[buf][k8 + tg    ][m0    ], ah[mi][0], al[mi][0]);
                split_tf32(As[buf][k8 + tg    ][m0 + 8], ah[mi][1], al[mi][1]);
                split_tf32(As[buf][k8 + tg + 4][m0    ], ah[mi][2], al[mi][2]);
                split_tf32(As[buf][k8 + tg + 4][m0 + 8], ah[mi][3], al[mi][3]);
            }
#pragma unroll
            for (int ni = 0; ni < 4; ni++) {
                const int n0 = nW + ni * 8 + g;
                split_tf32(Bs[buf][k8 + tg    ][n0], bh[ni][0], bl[ni][0]);
                split_tf32(Bs[buf][k8 + tg + 4][n0], bh[ni][1], bl[ni][1]);
            }
#pragma unroll
            for (int mi = 0; mi < 4; mi++)
#pragma unroll
                for (int ni = 0; ni < 4; ni++) {
                    mma8(acc[mi][ni], ah[mi][0], ah[mi][1], ah[mi][2], ah[mi][3],
                         bh[ni][0], bh[ni][1]);
                    mma8(acc[mi][ni], ah[mi][0], ah[mi][1], ah[mi][2], ah[mi][3],
                         bl[ni][0], bl[ni][1]);
                    mma8(acc[mi][ni], al[mi][0], al[mi][1], al[mi][2], al[mi][3],
                         bh[ni][0], bh[ni][1]);
                }
        }
        if (more) {
            stash(buf ^ 1);
            __syncthreads();
            buf ^= 1;
        }
    }

    // epilogue
    const float alpha = ALPHA ? *alphaPtr : 1.f;
#pragma unroll
    for (int mi = 0; mi < 4; mi++) {
        const int row0 = blockRow + mW + mi * 16 + g;
#pragma unroll
        for (int ni = 0; ni < 4; ni++) {
            const int col = blockCol + nW + ni * 8 + 2 * tg;
#pragma unroll
            for (int hr = 0; hr < 2; hr++) {
                const int row = row0 + 8 * hr;
                float v0 = acc[mi][ni][2 * hr + 0];
                float v1 = acc[mi][ni][2 * hr + 1];
                if (ALPHA) { v0 *= alpha; v1 *= alpha; }
                if (BIAS)  { v0 += bias[col]; v1 += bias[col + 1]; }
                if (GELU_ACT) {
                    v0 = 0.5f * v0 * (1.f + erff(v0 * 0.70710678118654752440f));
                    v1 = 0.5f * v1 * (1.f + erff(v1 * 0.70710678118654752440f));
                }
                const size_t off = (size_t)row * ldc + col;
                if (RES) {
                    const float2 r2 = *(const float2*)(R + off);
                    v0 += r2.x; v1 += r2.y;
                }
                *(float2*)(C + off) = make_float2(v0, v1);
            }
        }
    }
}

// ---------------- rel-shift + mask + softmax (in-place over QK) -------------------
__global__ __launch_bounds__(256) void softmax_rel_k(float* __restrict__ QK,
                                                     const float* __restrict__ QP)
{
    const int i = blockIdx.x;
    const int z = blockIdx.y;
    const int tid = threadIdx.x;
    const float scale = 0.08838834764831845f;   // DH^-0.5
    float* row = QK + ((size_t)z * SEQ + i) * KVL;
    const float* prow = QP + ((size_t)z * SEQ + i) * KVL + (SEQ - 1 - i);
    const int L = i + MEMN + LMEMN + 1;
    __shared__ float red[8];

    float sv[9];
    float m = -3.4e38f;
#pragma unroll
    for (int t = 0; t < 9; t++) {
        const int j = tid + 256 * t;
        float v = -3.4e38f;
        if (j < L) v = scale * (row[j] + prow[j]);
        sv[t] = v;
        m = fmaxf(m, v);
    }
#pragma unroll
    for (int off = 16; off; off >>= 1) m = fmaxf(m, __shfl_xor_sync(0xffffffffu, m, off));
    if ((tid & 31) == 0) red[tid >> 5] = m;
    __syncthreads();
    if (tid == 0) {
        float t = red[0];
#pragma unroll
        for (int r = 1; r < 8; r++) t = fmaxf(t, red[r]);
        red[0] = t;
    }
    __syncthreads();
    m = red[0];
    __syncthreads();
    float s = 0.f;
#pragma unroll
    for (int t = 0; t < 9; t++) {
        const int j = tid + 256 * t;
        float e = 0.f;
        if (j < L) e = expf(sv[t] - m);
        sv[t] = e;
        s += e;
    }
#pragma unroll
    for (int off = 16; off; off >>= 1) s += __shfl_xor_sync(0xffffffffu, s, off);
    if ((tid & 31) == 0) red[tid >> 5] = s;
    __syncthreads();
    if (tid == 0) {
        float t = 0.f;
#pragma unroll
        for (int r = 0; r < 8; r++) t += red[r];
        red[0] = 1.f / t;
    }
    __syncthreads();
    const float inv = red[0];
#pragma unroll
    for (int t = 0; t < 9; t++) {
        const int j = tid + 256 * t;
        row[j] = sv[t] * inv;       // zero beyond L (sv[t]==0 there)
    }
}

// ---------------- memnet: q softmax over DH per head (scale BEFORE softmax) -------
__global__ __launch_bounds__(256) void qsoftmax_k(float* __restrict__ Q)
{
    const float S = 0.29730177875068026f;       // DH^-0.25
    const int row = blockIdx.x;
    const int h = threadIdx.x >> 5;
    const int lane = threadIdx.x & 31;
    float* p = Q + (size_t)row * DIM + h * DH;
    float v0 = p[lane] * S, v1 = p[lane + 32] * S,
          v2 = p[lane + 64] * S, v3 = p[lane + 96] * S;
    float m = fmaxf(fmaxf(v0, v1), fmaxf(v2, v3));
#pragma unroll
    for (int off = 16; off; off >>= 1) m = fmaxf(m, __shfl_xor_sync(0xffffffffu, m, off));
    const float e0 = expf(v0 - m), e1 = expf(v1 - m),
                e2 = expf(v2 - m), e3 = expf(v3 - m);
    float s = e0 + e1 + e2 + e3;
#pragma unroll
    for (int off = 16; off; off >>= 1) s += __shfl_xor_sync(0xffffffffu, s, off);
    const float inv = 1.f / s;
    p[lane] = e0 * inv; p[lane + 32] = e1 * inv;
    p[lane + 64] = e2 * inv; p[lane + 96] = e3 * inv;
}

// ---------------- memnet: column-softmax stats for k (max and 1/sumexp per col) ---
__global__ __launch_bounds__(256) void kcolstat_k(const float* __restrict__ KV,
                                                  float* __restrict__ KM,
                                                  float* __restrict__ KI)
{
    const int mb = blockIdx.y;
    const int cx = threadIdx.x & 31;
    const int c = blockIdx.x * 32 + cx;
    const int ry = threadIdx.x >> 5;
    const float S = 0.29730177875068026f;
    const float* base = KV + (size_t)mb * KVL * (2 * DIM) + c;
    __shared__ float red[8][32];
    float m = -3.4e38f;
    for (int n = ry; n < KVL; n += 8) m = fmaxf(m, base[(size_t)n * (2 * DIM)]);
    red[ry][cx] = m;
    __syncthreads();
    if (ry == 0) {
#pragma unroll
        for (int r = 1; r < 8; r++) m = fmaxf(m, red[r][cx]);
        red[0][cx] = m;
    }
    __syncthreads();
    m = red[0][cx] * S;      // already scaled
    float s = 0.f;
    for (int n = ry; n < KVL; n += 8)
        s += expf(base[(size_t)n * (2 * DIM)] * S - m);
    __syncthreads();
    red[ry][cx] = s;
    __syncthreads();
    if (ry == 0) {
#pragma unroll
        for (int r = 1; r < 8; r++) s += red[r][cx];
        KM[mb * DIM + c] = m;
        KI[mb * DIM + c] = 1.f / s;
    }
}

// ---------------- memnet: ctx[d][e] = sum_n softmax(k)[n,d] * v[n,e] --------------
__global__ __launch_bounds__(256) void ctx_k(const float* __restrict__ KV,
                                             const float* __restrict__ KM,
                                             const float* __restrict__ KI,
                                             float* __restrict__ CTX)
{
    const int z = blockIdx.x;
    const int mb = z >> 3, h = z & 7;
    const float S = 0.29730177875068026f;
    __shared__ float ks[16][132];
    __shared__ float vs[16][132];
    const int tid = threadIdx.x;
    const int tx = tid & 15, ty = tid >> 4;
    const int c = tid & 127, r0 = tid >> 7;
    float acc[8][8];
#pragma unroll
    for (int a = 0; a < 8; a++)
#pragma unroll
        for (int b = 0; b < 8; b++) acc[a][b] = 0.f;

    const float* kvb = KV + (size_t)mb * KVL * (2 * DIM) + h * DH;
    const float kmc = KM[mb * DIM + h * DH + c];
    const float kic = KI[mb * DIM + h * DH + c];

    for (int n0 = 0; n0 < KVL; n0 += 16) {
#pragma unroll
        for (int p = 0; p < 8; p++) {
            const int r = r0 + p * 2;
            const size_t off = (size_t)(n0 + r) * (2 * DIM) + c;
            ks[r][c] = expf(kvb[off] * S - kmc) * kic;
            vs[r][c] = kvb[off + DIM];
        }
        __syncthreads();
#pragma unroll
        for (int kk = 0; kk < 16; kk++) {
            float ra[8], rb[8];
#pragma unroll
            for (int a = 0; a < 8; a++) ra[a] = ks[kk][ty * 8 + a];
#pragma unroll
            for (int b = 0; b < 8; b++) rb[b] = vs[kk][tx * 8 + b];
#pragma unroll
            for (int a = 0; a < 8; a++)
#pragma unroll
                for (int b = 0; b < 8; b++) acc[a][b] += ra[a] * rb[b];
        }
        __syncthreads();
    }
    float* ctx = CTX + (size_t)z * DH * DH;
#pragma unroll
    for (int a = 0; a < 8; a++)
#pragma unroll
        for (int b = 0; b < 8; b++)
            ctx[(ty * 8 + a) * DH + tx * 8 + b] = acc[a][b];
}

// ---------------- memnet: out[n][e] = sum_d q[n,d]*ctx[d,e]  (head-major output) --
__global__ __launch_bounds__(128) void memout_k(const float* __restrict__ Q,
                                                const float* __restrict__ CTX,
                                                float* __restrict__ O)
{
    const int z = blockIdx.x;
    const int mb = z >> 3, h = z & 7;
    const int n0 = blockIdx.y * 64;
    const int e = threadIdx.x;
    __shared__ float qs[128];
    const float* ctx = CTX + (size_t)z * DH * DH;
    for (int n = n0; n < n0 + 64; n++) {
        const size_t base = (size_t)(mb * LMEMN + n) * DIM + h * DH;
        qs[e] = Q[base + e];
        __syncthreads();
        float acc = 0.f;
#pragma unroll 16
        for (int d = 0; d < 128; d++) acc += qs[d] * ctx[d * DH + e];
        O[base + e] = acc;
        __syncthreads();
    }
}

// =================================================================================
extern "C" void kernel_launch(void* const* d_in, const int* in_sizes, int n_in,
                              void* d_out, int out_size)
{
    (void)in_sizes; (void)n_in; (void)out_size;
    const int*   x    = (const int*)  d_in[0];
    const float* mem  = (const float*)d_in[1];
    const float* lmem = (const float*)d_in[2];
    const float* temb = (const float*)d_in[3];
    const float* pemb = (const float*)d_in[4];
    const float* alng = (const float*)d_in[5];
    const float* alnb = (const float*)d_in[6];
    const float* wq   = (const float*)d_in[7];
    const float* wkv  = (const float*)d_in[8];
    const float* wo   = (const float*)d_in[9];
    const float* bo   = (const float*)d_in[10];
    const float* flng = (const float*)d_in[11];
    const float* flnb = (const float*)d_in[12];
    const float* w1   = (const float*)d_in[13];
    const float* b1   = (const float*)d_in[14];
    const float* w2   = (const float*)d_in[15];
    const float* b2   = (const float*)d_in[16];
    const float* lw   = (const float*)d_in[17];
    const float* lb   = (const float*)d_in[18];
    const float* mwq  = (const float*)d_in[19];
    const float* mwkv = (const float*)d_in[20];
    const float* mwo  = (const float*)d_in[21];
    const float* rez  = (const float*)d_in[22];

    float* out        = (float*)d_out;
    float* out_logits = out;
    float* out_nmem   = out + (size_t)BB * SEQ * VOCAB;
    float* out_nlmem  = out_nmem + (size_t)DEPTH * BB * MEMN * DIM;

    float *ph, *pn, *pq, *pkvin, *pkv, *ptmp, *pff, *pkm, *pki, *pctx, *pqk, *pqp;
    cudaGetSymbolAddress((void**)&ph,    g_h);
    cudaGetSymbolAddress((void**)&pn,    g_norm);
    cudaGetSymbolAddress((void**)&pq,    g_q);
    cudaGetSymbolAddress((void**)&pkvin, g_kvin);
    cudaGetSymbolAddress((void**)&pkv,   g_kv);
    cudaGetSymbolAddress((void**)&ptmp,  g_tmp);
    cudaGetSymbolAddress((void**)&pff,   g_ffmid);
    cudaGetSymbolAddress((void**)&pkm,   g_km);
    cudaGetSymbolAddress((void**)&pki,   g_ki);
    cudaGetSymbolAddress((void**)&pctx,  g_ctx);
    cudaGetSymbolAddress((void**)&pqk,   g_qk);
    cudaGetSymbolAddress((void**)&pqp,   g_qp);

    const int M = BB * SEQ;               // 2048
    const long sSKV = (long)SEQ * KVL;    // per-head score stride

    // h = token_emb[x]
    embed_k<<<M, 256>>>(x, temb, ph);

    for (int i = 0; i < DEPTH; i++) {
        // hiddens[i] = h  (== next_mem[i], since MEM == SEQ)
        cudaMemcpyAsync(out_nmem + (size_t)i * BB * MEMN * DIM, ph,
                        sizeof(float) * (size_t)M * DIM, cudaMemcpyDeviceToDevice);
        // a_in = LN(h)
        ln_k<<<M, 256>>>(ph, alng + (size_t)i * DIM, alnb + (size_t)i * DIM, pn);
        // Q = a_in @ wq
        tgemm_k<false,false,false,false,false><<<dim3(DIM/128, M/128, 1), 256>>>(
            pn, wq + (size_t)i * DIM * DIM, nullptr, nullptr, pq,
            DIM, DIM, DIM, DIM, 0,0,0,0,0,0, nullptr);
        // kv_in = [lmem[i] | mem[i] | a_in]
        for (int b = 0; b < BB; b++) {
            float* dst = pkvin + (size_t)b * KVL * DIM;
            cudaMemcpyAsync(dst, lmem + ((size_t)i * BB + b) * LMEMN * DIM,
                            sizeof(float) * LMEMN * DIM, cudaMemcpyDeviceToDevice);
            cudaMemcpyAsync(dst + (size_t)LMEMN * DIM,
                            mem + ((size_t)i * BB + b) * MEMN * DIM,
                            sizeof(float) * MEMN * DIM, cudaMemcpyDeviceToDevice);
            cudaMemcpyAsync(dst + (size_t)(LMEMN + MEMN) * DIM,
                            pn + (size_t)b * SEQ * DIM,
                            sizeof(float) * SEQ * DIM, cudaMemcpyDeviceToDevice);
        }
        // KV = kv_in @ wkv
        tgemm_k<false,false,false,false,false><<<dim3(2*DIM/128, BB*KVL/128, 1), 256>>>(
            pkvin, wkv + (size_t)i * DIM * 2 * DIM, nullptr, nullptr, pkv,
            DIM, 2*DIM, 2*DIM, DIM, 0,0,0,0,0,0, nullptr);
        // --- attention as batched tensor GEMMs ---
        // QK[z] = Q[b,:,h] @ K[b,:,h]^T        (z = b*8+h)
        tgemm_k<true,false,false,false,false><<<dim3(KVL/128, SEQ/128, BB*HEADS), 256>>>(
            pq, pkv, nullptr, nullptr, pqk,
            DIM, 2*DIM, KVL, DH,
            (long)SEQ*DIM, DH,
            (long)KVL*2*DIM, DH,
            (long)HEADS*sSKV, sSKV,
            nullptr);
        // QP[z] = Q[b,:,h] @ PE[h]^T
        tgemm_k<true,false,false,false,false><<<dim3(KVL/128, SEQ/128, BB*HEADS), 256>>>(
            pq, pemb, nullptr, nullptr, pqp,
            DIM, DH, KVL, DH,
            (long)SEQ*DIM, DH,
            0L, (long)KVL*DH,
            (long)HEADS*sSKV, sSKV,
            nullptr);
        // shift + mask + softmax (in place into pqk)
        softmax_rel_k<<<dim3(SEQ, BB*HEADS), 256>>>(pqk, pqp);
        // out[b,:,h] = attn[z] @ V[b,:,h]
        tgemm_k<false,false,false,false,false><<<dim3(DH/128, SEQ/128, BB*HEADS), 256>>>(
            pqk, pkv + DIM, nullptr, nullptr, ptmp,
            KVL, 2*DIM, DIM, KVL,
            (long)HEADS*sSKV, sSKV,
            (long)KVL*2*DIM, DH,
            (long)SEQ*DIM, DH,
            nullptr);
        // h = h + attn_out @ wo + bo
        tgemm_k<false,true,true,false,false><<<dim3(DIM/128, M/128, 1), 256>>>(
            ptmp, wo + (size_t)i * DIM * DIM, bo + (size_t)i * DIM, ph, ph,
            DIM, DIM, DIM, DIM, 0,0,0,0,0,0, nullptr);
        // f_in = LN(h)
        ln_k<<<M, 256>>>(ph, flng + (size_t)i * DIM, flnb + (size_t)i * DIM, pn);
        // mid = gelu(f_in @ w1 + b1)
        tgemm_k<false,true,false,true,false><<<dim3(FFD/128, M/128, 1), 256>>>(
            pn, w1 + (size_t)i * DIM * FFD, b1 + (size_t)i * FFD, nullptr, pff,
            DIM, FFD, FFD, DIM, 0,0,0,0,0,0, nullptr);
        // h = h + mid @ w2 + b2
        tgemm_k<false,true,true,false,false><<<dim3(DIM/128, M/128, 1), 256>>>(
            pff, w2 + (size_t)i * FFD * DIM, b2 + (size_t)i * DIM, ph, ph,
            FFD, DIM, DIM, FFD, 0,0,0,0,0,0, nullptr);
    }

    // logits = h @ logits_w + logits_b
    tgemm_k<false,true,false,false,false><<<dim3(VOCAB/128, M/128, 1), 256>>>(
        ph, lw, lb, nullptr, out_logits,
        DIM, VOCAB, VOCAB, DIM, 0,0,0,0,0,0, nullptr);

    // ---------------- memory network ----------------
    const int MR = DEPTH * BB * LMEMN;    // 2048 rows of lmem
    // nl = LN(lmem)  (no affine)
    ln_k<<<MR, 256>>>(lmem, nullptr, nullptr, pn);
    // q = nl @ mem_wq, then per-head softmax over DH (scaled first)
    tgemm_k<false,false,false,false,false><<<dim3(DIM/128, MR/128, 1), 256>>>(
        pn, mwq, nullptr, nullptr, pq,
        DIM, DIM, DIM, DIM, 0,0,0,0,0,0, nullptr);
    qsoftmax_k<<<MR, 256>>>(pq);
    // kv_in = [nl | mem | hiddens]  per (m,b)
    for (int i = 0; i < DEPTH; i++)
        for (int b = 0; b < BB; b++) {
            const int mb = i * BB + b;
            float* dst = pkvin + (size_t)mb * KVL * DIM;
            cudaMemcpyAsync(dst, pn + (size_t)mb * LMEMN * DIM,
                            sizeof(float) * LMEMN * DIM, cudaMemcpyDeviceToDevice);
            cudaMemcpyAsync(dst + (size_t)LMEMN * DIM,
                            mem + (size_t)mb * MEMN * DIM,
                            sizeof(float) * MEMN * DIM, cudaMemcpyDeviceToDevice);
            cudaMemcpyAsync(dst + (size_t)(LMEMN + MEMN) * DIM,
                            out_nmem + (size_t)mb * MEMN * DIM,
                            sizeof(float) * MEMN * DIM, cudaMemcpyDeviceToDevice);
        }
    // KV = kv_in @ mem_wkv
    tgemm_k<false,false,false,false,false><<<dim3(2*DIM/128, DEPTH*BB*KVL/128, 1), 256>>>(
        pkvin, mwkv, nullptr, nullptr, pkv,
        DIM, 2*DIM, 2*DIM, DIM, 0,0,0,0,0,0, nullptr);
    // column softmax stats for k, then ctx = softk^T v, out = q @ ctx
    kcolstat_k<<<dim3(DIM/32, DEPTH*BB), 256>>>(pkv, pkm, pki);
    ctx_k<<<DEPTH*BB*HEADS, 256>>>(pkv, pkm, pki, pctx);
    memout_k<<<dim3(DEPTH*BB*HEADS, LMEMN/64), 128>>>(pq, pctx, ptmp);
    // next_lmem = out @ mem_wo * rezero + lmem
    tgemm_k<false,false,true,false,true><<<dim3(DIM/128, MR/128, 1), 256>>>(
        ptmp, mwo, nullptr, lmem, out_nlmem,
        DIM, DIM, DIM, DIM, 0,0,0,0,0,0, rez);
}

// round 14
// speedup vs baseline: 3.4242x; 1.0063x over previous
#include <cuda_runtime.h>
#include <math.h>
#include <stdint.h>

#define BB     2
#define SEQ    1024
#define DIM    1024
#define HEADS  8
#define DH     128
#define MEMN   1024
#define LMEMN  256
#define KVL    2304          // LMEM + MEM + SEQ
#define DEPTH  4
#define VOCAB  32000
#define FFD    4096

// dynamic SMEM for tgemm_k: 4 arrays [2][16][136] floats
#define TGP    136
#define TG_ARR (2*16*TGP)
#define TG_SMEM (4*TG_ARR*4)      // 69632 bytes

// ---------------- scratch (allocation-free: __device__ globals) ----------------
__device__ float g_h[BB*SEQ*DIM];                  // residual stream        (8 MB)
__device__ float g_norm[BB*SEQ*DIM];               // LN output / memnet nl  (8 MB)
__device__ float g_q[BB*SEQ*DIM];                  // Q / memnet q           (8 MB)
__device__ float g_kvin[DEPTH*BB*KVL*DIM];         // kv_in                  (75.5 MB)
__device__ float g_kv[DEPTH*BB*KVL*2*DIM];         // kv = kv_in @ wkv       (151 MB)
__device__ float g_tmp[BB*SEQ*DIM];                // attn out / memnet out  (8 MB)
__device__ float g_ffmid[BB*SEQ*FFD];              // FF hidden              (33.5 MB)
__device__ float g_km[DEPTH*BB*DIM];               // memnet k col max*S
__device__ float g_ki[DEPTH*BB*DIM];               // memnet k col 1/sumexp
__device__ float g_ctx[DEPTH*BB*HEADS*DH*DH];      // memnet ctx             (4 MB)
__device__ float g_qk[BB*HEADS*SEQ*KVL];           // QK scores / attn       (151 MB)
__device__ float g_qp[BB*HEADS*SEQ*KVL];           // Q @ PE^T               (151 MB)

// ---------------- embedding ----------------
__global__ void embed_k(const int* __restrict__ X, const float* __restrict__ E,
                        float* __restrict__ H)
{
    const int row = blockIdx.x;
    const int tok = X[row];
    const float4* src = (const float4*)(E + (size_t)tok * DIM);
    float4* dst = (float4*)(H + (size_t)row * DIM);
    dst[threadIdx.x] = src[threadIdx.x];
}

// ---------------- LayerNorm over last dim (1024), optional affine ----------------
__global__ __launch_bounds__(256) void ln_k(const float* __restrict__ X,
                                            const float* __restrict__ G,
                                            const float* __restrict__ Bp,
                                            float* __restrict__ Y)
{
    const int tid = threadIdx.x;
    const float4 v = ((const float4*)(X + (size_t)blockIdx.x * DIM))[tid];
    __shared__ float red[8];
    float s = v.x + v.y + v.z + v.w;
#pragma unroll
    for (int off = 16; off; off >>= 1) s += __shfl_xor_sync(0xffffffffu, s, off);
    if ((tid & 31) == 0) red[tid >> 5] = s;
    __syncthreads();
    if (tid == 0) {
        float t = 0.f;
#pragma unroll
        for (int r = 0; r < 8; r++) t += red[r];
        red[0] = t * (1.f / DIM);
    }
    __syncthreads();
    const float mu = red[0];
    __syncthreads();
    const float dx = v.x - mu, dy = v.y - mu, dz = v.z - mu, dw = v.w - mu;
    float ss = dx*dx + dy*dy + dz*dz + dw*dw;
#pragma unroll
    for (int off = 16; off; off >>= 1) ss += __shfl_xor_sync(0xffffffffu, ss, off);
    if ((tid & 31) == 0) red[tid >> 5] = ss;
    __syncthreads();
    if (tid == 0) {
        float t = 0.f;
#pragma unroll
        for (int r = 0; r < 8; r++) t += red[r];
        red[0] = rsqrtf(t * (1.f / DIM) + 1e-5f);
    }
    __syncthreads();
    const float rstd = red[0];
    float4 o;
    o.x = dx * rstd; o.y = dy * rstd; o.z = dz * rstd; o.w = dw * rstd;
    if (G != nullptr) {
        const float4 g4 = ((const float4*)G)[tid];
        const float4 b4 = ((const float4*)Bp)[tid];
        o.x = o.x * g4.x + b4.x;
        o.y = o.y * g4.y + b4.y;
        o.z = o.z * g4.z + b4.z;
        o.w = o.w * g4.w + b4.w;
    }
    ((float4*)(Y + (size_t)blockIdx.x * DIM))[tid] = o;
}

// ---------------- tf32 helpers ----------------
__device__ __forceinline__ void split_tf32(float x, uint32_t& hi, uint32_t& lo)
{
    asm("cvt.rna.tf32.f32 %0, %1;" : "=r"(hi) : "f"(x));
    const float l = x - __uint_as_float(hi);
    asm("cvt.rna.tf32.f32 %0, %1;" : "=r"(lo) : "f"(l));
}

__device__ __forceinline__ void mma8(float c[4],
                                     uint32_t a0, uint32_t a1, uint32_t a2, uint32_t a3,
                                     uint32_t b0, uint32_t b1)
{
    asm volatile(
        "mma.sync.aligned.m16n8k8.row.col.f32.tf32.tf32.f32 "
        "{%0,%1,%2,%3}, {%4,%5,%6,%7}, {%8,%9}, {%0,%1,%2,%3};"
        : "+f"(c[0]), "+f"(c[1]), "+f"(c[2]), "+f"(c[3])
        : "r"(a0), "r"(a1), "r"(a2), "r"(a3), "r"(b0), "r"(b1));
}

// ---------------- unified tensor-core GEMM (3xTF32, pre-split SMEM) ---------------
// C = act(A@op(B) * alpha + bias) + res.  A row-major MxK.
// BT=true : B is N x K row-major (NT GEMM).  BT=false: B is K x N row-major (NN).
// 128x128 block tile, BK=16, 8 warps each computing 64x32 via m16n8k8 mma.
// hi/lo tf32 split done ONCE at staging; inner loop is pure LDS + MMA.
// Requires M%128==0, N%128==0, K%16==0. Batched over gridDim.z (z = bb*8+hh).
template<bool BT, bool BIAS, bool RES, bool GELU_ACT, bool ALPHA>
__global__ __launch_bounds__(256, 1) void tgemm_k(
    const float* __restrict__ A, const float* __restrict__ B,
    const float* __restrict__ bias, const float* __restrict__ R,
    float* __restrict__ C,
    int lda, int ldb, int ldc, int K,
    long sAb, long sAh, long sBb, long sBh, long sCb, long sCh,
    const float* __restrict__ alphaPtr)
{
    extern __shared__ float dsm[];
    float* Ah = dsm;
    float* Al = Ah + TG_ARR;
    float* Bh = Al + TG_ARR;
    float* Bl = Bh + TG_ARR;

    const int bb = blockIdx.z >> 3, hh = blockIdx.z & 7;
    A += bb * sAb + hh * sAh;
    B += bb * sBb + hh * sBh;
    C += bb * sCb + hh * sCh;

    const int tid  = threadIdx.x;
    const int lane = tid & 31, warp = tid >> 5;
    const int g  = lane >> 2, tg = lane & 3;
    const int mW = (warp >> 2) * 64;     // warp row base (0 or 64)
    const int nW = (warp & 3) * 32;      // warp col base
    const int blockRow = blockIdx.y * 128;
    const int blockCol = blockIdx.x * 128;

    // staging assignment
    const int sM = tid >> 1;             // 0..127
    const int sK = (tid & 1) * 8;        // 0 or 8
    const float* aSrc = A + (size_t)(blockRow + sM) * lda + sK;
    const float* bSrc;
    int bK = 0, bN = 0;
    if (BT) {
        bSrc = B + (size_t)(blockCol + sM) * ldb + sK;
    } else {
        bK = tid >> 4;                   // 0..15
        bN = (tid & 15) * 8;             // 0..120
        bSrc = B + (size_t)bK * ldb + blockCol + bN;
    }

    float4 ar0, ar1, br0, br1;
    auto stash = [&](int sb) {
        const float av[8] = {ar0.x, ar0.y, ar0.z, ar0.w, ar1.x, ar1.y, ar1.z, ar1.w};
#pragma unroll
        for (int j = 0; j < 8; j++) {
            uint32_t h, l;
            split_tf32(av[j], h, l);
            Ah[(sb * 16 + sK + j) * TGP + sM] = __uint_as_float(h);
            Al[(sb * 16 + sK + j) * TGP + sM] = __uint_as_float(l);
        }
        const float bv[8] = {br0.x, br0.y, br0.z, br0.w, br1.x, br1.y, br1.z, br1.w};
        if (BT) {
#pragma unroll
            for (int j = 0; j < 8; j++) {
                uint32_t h, l;
                split_tf32(bv[j], h, l);
                Bh[(sb * 16 + sK + j) * TGP + sM] = __uint_as_float(h);
                Bl[(sb * 16 + sK + j) * TGP + sM] = __uint_as_float(l);
            }
        } else {
            uint32_t h[8], l[8];
#pragma unroll
            for (int j = 0; j < 8; j++) split_tf32(bv[j], h[j], l[j]);
            float* ph_ = &Bh[(sb * 16 + bK) * TGP + bN];
            float* pl_ = &Bl[(sb * 16 + bK) * TGP + bN];
            *(uint4*)(ph_)     = make_uint4(h[0], h[1], h[2], h[3]);
            *(uint4*)(ph_ + 4) = make_uint4(h[4], h[5], h[6], h[7]);
            *(uint4*)(pl_)     = make_uint4(l[0], l[1], l[2], l[3]);
            *(uint4*)(pl_ + 4) = make_uint4(l[4], l[5], l[6], l[7]);
        }
    };

    // stage 0
    ar0 = *(const float4*)(aSrc);
    ar1 = *(const float4*)(aSrc + 4);
    br0 = *(const float4*)(bSrc);
    br1 = *(const float4*)(bSrc + 4);
    stash(0);
    __syncthreads();

    float acc[4][4][4];
#pragma unroll
    for (int mi = 0; mi < 4; mi++)
#pragma unroll
        for (int ni = 0; ni < 4; ni++)
#pragma unroll
            for (int r = 0; r < 4; r++) acc[mi][ni][r] = 0.f;

    int buf = 0;
    for (int k0 = 0; k0 < K; k0 += 16) {
        const bool more = (k0 + 16 < K);
        if (more) {
            ar0 = *(const float4*)(aSrc + k0 + 16);
            ar1 = *(const float4*)(aSrc + k0 + 20);
            if (BT) {
                br0 = *(const float4*)(bSrc + k0 + 16);
                br1 = *(const float4*)(bSrc + k0 + 20);
            } else {
                const float* p = bSrc + (size_t)(k0 + 16) * ldb;
                br0 = *(const float4*)(p);
                br1 = *(const float4*)(p + 4);
            }
        }
#pragma unroll
        for (int k8 = 0; k8 < 16; k8 += 8) {
            const int kb = buf * 16 + k8;
            uint32_t ah[4][4], al[4][4], bh[4][2], bl[4][2];
#pragma unroll
            for (int mi = 0; mi < 4; mi++) {
                const int m0 = mW + mi * 16 + g;
                const int r0 = (kb + tg) * TGP;
                const int r1 = (kb + tg + 4) * TGP;
                ah[mi][0] = __float_as_uint(Ah[r0 + m0]);
                ah[mi][1] = __float_as_uint(Ah[r0 + m0 + 8]);
                ah[mi][2] = __float_as_uint(Ah[r1 + m0]);
                ah[mi][3] = __float_as_uint(Ah[r1 + m0 + 8]);
                al[mi][0] = __float_as_uint(Al[r0 + m0]);
                al[mi][1] = __float_as_uint(Al[r0 + m0 + 8]);
                al[mi][2] = __float_as_uint(Al[r1 + m0]);
                al[mi][3] = __float_as_uint(Al[r1 + m0 + 8]);
            }
#pragma unroll
            for (int ni = 0; ni < 4; ni++) {
                const int n0 = nW + ni * 8 + g;
                bh[ni][0] = __float_as_uint(Bh[(kb + tg) * TGP + n0]);
                bh[ni][1] = __float_as_uint(Bh[(kb + tg + 4) * TGP + n0]);
                bl[ni][0] = __float_as_uint(Bl[(kb + tg) * TGP + n0]);
                bl[ni][1] = __float_as_uint(Bl[(kb + tg + 4) * TGP + n0]);
            }
#pragma unroll
            for (int mi = 0; mi < 4; mi++)
#pragma unroll
                for (int ni = 0; ni < 4; ni++) {
                    mma8(acc[mi][ni], ah[mi][0], ah[mi][1], ah[mi][2], ah[mi][3],
                         bh[ni][0], bh[ni][1]);
                    mma8(acc[mi][ni], ah[mi][0], ah[mi][1], ah[mi][2], ah[mi][3],
                         bl[ni][0], bl[ni][1]);
                    mma8(acc[mi][ni], al[mi][0], al[mi][1], al[mi][2], al[mi][3],
                         bh[ni][0], bh[ni][1]);
                }
        }
        if (more) {
            stash(buf ^ 1);
            __syncthreads();
            buf ^= 1;
        }
    }

    // epilogue
    const float alpha = ALPHA ? *alphaPtr : 1.f;
#pragma unroll
    for (int mi = 0; mi < 4; mi++) {
        const int row0 = blockRow + mW + mi * 16 + g;
#pragma unroll
        for (int ni = 0; ni < 4; ni++) {
            const int col = blockCol + nW + ni * 8 + 2 * tg;
#pragma unroll
            for (int hr = 0; hr < 2; hr++) {
                const int row = row0 + 8 * hr;
                float v0 = acc[mi][ni][2 * hr + 0];
                float v1 = acc[mi][ni][2 * hr + 1];
                if (ALPHA) { v0 *= alpha; v1 *= alpha; }
                if (BIAS)  { v0 += bias[col]; v1 += bias[col + 1]; }
                if (GELU_ACT) {
                    v0 = 0.5f * v0 * (1.f + erff(v0 * 0.70710678118654752440f));
                    v1 = 0.5f * v1 * (1.f + erff(v1 * 0.70710678118654752440f));
                }
                const size_t off = (size_t)row * ldc + col;
                if (RES) {
                    const float2 r2 = *(const float2*)(R + off);
                    v0 += r2.x; v1 += r2.y;
                }
                *(float2*)(C + off) = make_float2(v0, v1);
            }
        }
    }
}

// ---------------- rel-shift + mask + softmax (in-place over QK) -------------------
__global__ __launch_bounds__(256) void softmax_rel_k(float* __restrict__ QK,
                                                     const float* __restrict__ QP)
{
    const int i = blockIdx.x;
    const int z = blockIdx.y;
    const int tid = threadIdx.x;
    const float scale = 0.08838834764831845f;   // DH^-0.5
    float* row = QK + ((size_t)z * SEQ + i) * KVL;
    const float* prow = QP + ((size_t)z * SEQ + i) * KVL + (SEQ - 1 - i);
    const int L = i + MEMN + LMEMN + 1;
    __shared__ float red[8];

    float sv[9];
    float m = -3.4e38f;
#pragma unroll
    for (int t = 0; t < 9; t++) {
        const int j = tid + 256 * t;
        float v = -3.4e38f;
        if (j < L) v = scale * (row[j] + prow[j]);
        sv[t] = v;
        m = fmaxf(m, v);
    }
#pragma unroll
    for (int off = 16; off; off >>= 1) m = fmaxf(m, __shfl_xor_sync(0xffffffffu, m, off));
    if ((tid & 31) == 0) red[tid >> 5] = m;
    __syncthreads();
    if (tid == 0) {
        float t = red[0];
#pragma unroll
        for (int r = 1; r < 8; r++) t = fmaxf(t, red[r]);
        red[0] = t;
    }
    __syncthreads();
    m = red[0];
    __syncthreads();
    float s = 0.f;
#pragma unroll
    for (int t = 0; t < 9; t++) {
        const int j = tid + 256 * t;
        float e = 0.f;
        if (j < L) e = expf(sv[t] - m);
        sv[t] = e;
        s += e;
    }
#pragma unroll
    for (int off = 16; off; off >>= 1) s += __shfl_xor_sync(0xffffffffu, s, off);
    if ((tid & 31) == 0) red[tid >> 5] = s;
    __syncthreads();
    if (tid == 0) {
        float t = 0.f;
#pragma unroll
        for (int r = 0; r < 8; r++) t += red[r];
        red[0] = 1.f / t;
    }
    __syncthreads();
    const float inv = red[0];
#pragma unroll
    for (int t = 0; t < 9; t++) {
        const int j = tid + 256 * t;
        row[j] = sv[t] * inv;       // zero beyond L (sv[t]==0 there)
    }
}

// ---------------- memnet: q softmax over DH per head (scale BEFORE softmax) -------
__global__ __launch_bounds__(256) void qsoftmax_k(float* __restrict__ Q)
{
    const float S = 0.29730177875068026f;       // DH^-0.25
    const int row = blockIdx.x;
    const int h = threadIdx.x >> 5;
    const int lane = threadIdx.x & 31;
    float* p = Q + (size_t)row * DIM + h * DH;
    float v0 = p[lane] * S, v1 = p[lane + 32] * S,
          v2 = p[lane + 64] * S, v3 = p[lane + 96] * S;
    float m = fmaxf(fmaxf(v0, v1), fmaxf(v2, v3));
#pragma unroll
    for (int off = 16; off; off >>= 1) m = fmaxf(m, __shfl_xor_sync(0xffffffffu, m, off));
    const float e0 = expf(v0 - m), e1 = expf(v1 - m),
                e2 = expf(v2 - m), e3 = expf(v3 - m);
    float s = e0 + e1 + e2 + e3;
#pragma unroll
    for (int off = 16; off; off >>= 1) s += __shfl_xor_sync(0xffffffffu, s, off);
    const float inv = 1.f / s;
    p[lane] = e0 * inv; p[lane + 32] = e1 * inv;
    p[lane + 64] = e2 * inv; p[lane + 96] = e3 * inv;
}

// ---------------- memnet: column-softmax stats for k (max and 1/sumexp per col) ---
__global__ __launch_bounds__(256) void kcolstat_k(const float* __restrict__ KV,
                                                  float* __restrict__ KM,
                                                  float* __restrict__ KI)
{
    const int mb = blockIdx.y;
    const int cx = threadIdx.x & 31;
    const int c = blockIdx.x * 32 + cx;
    const int ry = threadIdx.x >> 5;
    const float S = 0.29730177875068026f;
    const float* base = KV + (size_t)mb * KVL * (2 * DIM) + c;
    __shared__ float red[8][32];
    float m = -3.4e38f;
    for (int n = ry; n < KVL; n += 8) m = fmaxf(m, base[(size_t)n * (2 * DIM)]);
    red[ry][cx] = m;
    __syncthreads();
    if (ry == 0) {
#pragma unroll
        for (int r = 1; r < 8; r++) m = fmaxf(m, red[r][cx]);
        red[0][cx] = m;
    }
    __syncthreads();
    m = red[0][cx] * S;      // already scaled
    float s = 0.f;
    for (int n = ry; n < KVL; n += 8)
        s += expf(base[(size_t)n * (2 * DIM)] * S - m);
    __syncthreads();
    red[ry][cx] = s;
    __syncthreads();
    if (ry == 0) {
#pragma unroll
        for (int r = 1; r < 8; r++) s += red[r][cx];
        KM[mb * DIM + c] = m;
        KI[mb * DIM + c] = 1.f / s;
    }
}

// ---------------- memnet: ctx[d][e] = sum_n softmax(k)[n,d] * v[n,e] --------------
__global__ __launch_bounds__(256) void ctx_k(const float* __restrict__ KV,
                                             const float* __restrict__ KM,
                                             const float* __restrict__ KI,
                                             float* __restrict__ CTX)
{
    const int z = blockIdx.x;
    const int mb = z >> 3, h = z & 7;
    const float S = 0.29730177875068026f;
    __shared__ float ks[16][132];
    __shared__ float vs[16][132];
    const int tid = threadIdx.x;
    const int tx = tid & 15, ty = tid >> 4;
    const int c = tid & 127, r0 = tid >> 7;
    float acc[8][8];
#pragma unroll
    for (int a = 0; a < 8; a++)
#pragma unroll
        for (int b = 0; b < 8; b++) acc[a][b] = 0.f;

    const float* kvb = KV + (size_t)mb * KVL * (2 * DIM) + h * DH;
    const float kmc = KM[mb * DIM + h * DH + c];
    const float kic = KI[mb * DIM + h * DH + c];

    for (int n0 = 0; n0 < KVL; n0 += 16) {
#pragma unroll
        for (int p = 0; p < 8; p++) {
            const int r = r0 + p * 2;
            const size_t off = (size_t)(n0 + r) * (2 * DIM) + c;
            ks[r][c] = expf(kvb[off] * S - kmc) * kic;
            vs[r][c] = kvb[off + DIM];
        }
        __syncthreads();
#pragma unroll
        for (int kk = 0; kk < 16; kk++) {
            float ra[8], rb[8];
#pragma unroll
            for (int a = 0; a < 8; a++) ra[a] = ks[kk][ty * 8 + a];
#pragma unroll
            for (int b = 0; b < 8; b++) rb[b] = vs[kk][tx * 8 + b];
#pragma unroll
            for (int a = 0; a < 8; a++)
#pragma unroll
                for (int b = 0; b < 8; b++) acc[a][b] += ra[a] * rb[b];
        }
        __syncthreads();
    }
    float* ctx = CTX + (size_t)z * DH * DH;
#pragma unroll
    for (int a = 0; a < 8; a++)
#pragma unroll
        for (int b = 0; b < 8; b++)
            ctx[(ty * 8 + a) * DH + tx * 8 + b] = acc[a][b];
}

// ---------------- memnet: out[n][e] = sum_d q[n,d]*ctx[d,e]  (head-major output) --
__global__ __launch_bounds__(128) void memout_k(const float* __restrict__ Q,
                                                const float* __restrict__ CTX,
                                                float* __restrict__ O)
{
    const int z = blockIdx.x;
    const int mb = z >> 3, h = z & 7;
    const int n0 = blockIdx.y * 64;
    const int e = threadIdx.x;
    __shared__ float qs[128];
    const float* ctx = CTX + (size_t)z * DH * DH;
    for (int n = n0; n < n0 + 64; n++) {
        const size_t base = (size_t)(mb * LMEMN + n) * DIM + h * DH;
        qs[e] = Q[base + e];
        __syncthreads();
        float acc = 0.f;
#pragma unroll 16
        for (int d = 0; d < 128; d++) acc += qs[d] * ctx[d * DH + e];
        O[base + e] = acc;
        __syncthreads();
    }
}

// =================================================================================
extern "C" void kernel_launch(void* const* d_in, const int* in_sizes, int n_in,
                              void* d_out, int out_size)
{
    (void)in_sizes; (void)n_in; (void)out_size;
    const int*   x    = (const int*)  d_in[0];
    const float* mem  = (const float*)d_in[1];
    const float* lmem = (const float*)d_in[2];
    const float* temb = (const float*)d_in[3];
    const float* pemb = (const float*)d_in[4];
    const float* alng = (const float*)d_in[5];
    const float* alnb = (const float*)d_in[6];
    const float* wq   = (const float*)d_in[7];
    const float* wkv  = (const float*)d_in[8];
    const float* wo   = (const float*)d_in[9];
    const float* bo   = (const float*)d_in[10];
    const float* flng = (const float*)d_in[11];
    const float* flnb = (const float*)d_in[12];
    const float* w1   = (const float*)d_in[13];
    const float* b1   = (const float*)d_in[14];
    const float* w2   = (const float*)d_in[15];
    const float* b2   = (const float*)d_in[16];
    const float* lw   = (const float*)d_in[17];
    const float* lb   = (const float*)d_in[18];
    const float* mwq  = (const float*)d_in[19];
    const float* mwkv = (const float*)d_in[20];
    const float* mwo  = (const float*)d_in[21];
    const float* rez  = (const float*)d_in[22];

    // raise dynamic-SMEM cap for every tgemm instantiation we use (idempotent)
    cudaFuncSetAttribute(tgemm_k<false,false,false,false,false>,
                         cudaFuncAttributeMaxDynamicSharedMemorySize, TG_SMEM);
    cudaFuncSetAttribute(tgemm_k<true,false,false,false,false>,
                         cudaFuncAttributeMaxDynamicSharedMemorySize, TG_SMEM);
    cudaFuncSetAttribute(tgemm_k<false,true,true,false,false>,
                         cudaFuncAttributeMaxDynamicSharedMemorySize, TG_SMEM);
    cudaFuncSetAttribute(tgemm_k<false,true,false,true,false>,
                         cudaFuncAttributeMaxDynamicSharedMemorySize, TG_SMEM);
    cudaFuncSetAttribute(tgemm_k<false,true,false,false,false>,
                         cudaFuncAttributeMaxDynamicSharedMemorySize, TG_SMEM);
    cudaFuncSetAttribute(tgemm_k<false,false,true,false,true>,
                         cudaFuncAttributeMaxDynamicSharedMemorySize, TG_SMEM);

    float* out        = (float*)d_out;
    float* out_logits = out;
    float* out_nmem   = out + (size_t)BB * SEQ * VOCAB;
    float* out_nlmem  = out_nmem + (size_t)DEPTH * BB * MEMN * DIM;

    float *ph, *pn, *pq, *pkvin, *pkv, *ptmp, *pff, *pkm, *pki, *pctx, *pqk, *pqp;
    cudaGetSymbolAddress((void**)&ph,    g_h);
    cudaGetSymbolAddress((void**)&pn,    g_norm);
    cudaGetSymbolAddress((void**)&pq,    g_q);
    cudaGetSymbolAddress((void**)&pkvin, g_kvin);
    cudaGetSymbolAddress((void**)&pkv,   g_kv);
    cudaGetSymbolAddress((void**)&ptmp,  g_tmp);
    cudaGetSymbolAddress((void**)&pff,   g_ffmid);
    cudaGetSymbolAddress((void**)&pkm,   g_km);
    cudaGetSymbolAddress((void**)&pki,   g_ki);
    cudaGetSymbolAddress((void**)&pctx,  g_ctx);
    cudaGetSymbolAddress((void**)&pqk,   g_qk);
    cudaGetSymbolAddress((void**)&pqp,   g_qp);

    const int M = BB * SEQ;               // 2048
    const long sSKV = (long)SEQ * KVL;    // per-head score stride

    // h = token_emb[x]
    embed_k<<<M, 256>>>(x, temb, ph);

    for (int i = 0; i < DEPTH; i++) {
        // hiddens[i] = h  (== next_mem[i], since MEM == SEQ)
        cudaMemcpyAsync(out_nmem + (size_t)i * BB * MEMN * DIM, ph,
                        sizeof(float) * (size_t)M * DIM, cudaMemcpyDeviceToDevice);
        // a_in = LN(h)
        ln_k<<<M, 256>>>(ph, alng + (size_t)i * DIM, alnb + (size_t)i * DIM, pn);
        // Q = a_in @ wq
        tgemm_k<false,false,false,false,false><<<dim3(DIM/128, M/128, 1), 256, TG_SMEM>>>(
            pn, wq + (size_t)i * DIM * DIM, nullptr, nullptr, pq,
            DIM, DIM, DIM, DIM, 0,0,0,0,0,0, nullptr);
        // kv_in = [lmem[i] | mem[i] | a_in]
        for (int b = 0; b < BB; b++) {
            float* dst = pkvin + (size_t)b * KVL * DIM;
            cudaMemcpyAsync(dst, lmem + ((size_t)i * BB + b) * LMEMN * DIM,
                            sizeof(float) * LMEMN * DIM, cudaMemcpyDeviceToDevice);
            cudaMemcpyAsync(dst + (size_t)LMEMN * DIM,
                            mem + ((size_t)i * BB + b) * MEMN * DIM,
                            sizeof(float) * MEMN * DIM, cudaMemcpyDeviceToDevice);
            cudaMemcpyAsync(dst + (size_t)(LMEMN + MEMN) * DIM,
                            pn + (size_t)b * SEQ * DIM,
                            sizeof(float) * SEQ * DIM, cudaMemcpyDeviceToDevice);
        }
        // KV = kv_in @ wkv
        tgemm_k<false,false,false,false,false><<<dim3(2*DIM/128, BB*KVL/128, 1), 256, TG_SMEM>>>(
            pkvin, wkv + (size_t)i * DIM * 2 * DIM, nullptr, nullptr, pkv,
            DIM, 2*DIM, 2*DIM, DIM, 0,0,0,0,0,0, nullptr);
        // --- attention as batched tensor GEMMs ---
        // QK[z] = Q[b,:,h] @ K[b,:,h]^T        (z = b*8+h)
        tgemm_k<true,false,false,false,false><<<dim3(KVL/128, SEQ/128, BB*HEADS), 256, TG_SMEM>>>(
            pq, pkv, nullptr, nullptr, pqk,
            DIM, 2*DIM, KVL, DH,
            (long)SEQ*DIM, DH,
            (long)KVL*2*DIM, DH,
            (long)HEADS*sSKV, sSKV,
            nullptr);
        // QP[z] = Q[b,:,h] @ PE[h]^T
        tgemm_k<true,false,false,false,false><<<dim3(KVL/128, SEQ/128, BB*HEADS), 256, TG_SMEM>>>(
            pq, pemb, nullptr, nullptr, pqp,
            DIM, DH, KVL, DH,
            (long)SEQ*DIM, DH,
            0L, (long)KVL*DH,
            (long)HEADS*sSKV, sSKV,
            nullptr);
        // shift + mask + softmax (in place into pqk)
        softmax_rel_k<<<dim3(SEQ, BB*HEADS), 256>>>(pqk, pqp);
        // out[b,:,h] = attn[z] @ V[b,:,h]
        tgemm_k<false,false,false,false,false><<<dim3(DH/128, SEQ/128, BB*HEADS), 256, TG_SMEM>>>(
            pqk, pkv + DIM, nullptr, nullptr, ptmp,
            KVL, 2*DIM, DIM, KVL,
            (long)HEADS*sSKV, sSKV,
            (long)KVL*2*DIM, DH,
            (long)SEQ*DIM, DH,
            nullptr);
        // h = h + attn_out @ wo + bo
        tgemm_k<false,true,true,false,false><<<dim3(DIM/128, M/128, 1), 256, TG_SMEM>>>(
            ptmp, wo + (size_t)i * DIM * DIM, bo + (size_t)i * DIM, ph, ph,
            DIM, DIM, DIM, DIM, 0,0,0,0,0,0, nullptr);
        // f_in = LN(h)
        ln_k<<<M, 256>>>(ph, flng + (size_t)i * DIM, flnb + (size_t)i * DIM, pn);
        // mid = gelu(f_in @ w1 + b1)
        tgemm_k<false,true,false,true,false><<<dim3(FFD/128, M/128, 1), 256, TG_SMEM>>>(
            pn, w1 + (size_t)i * DIM * FFD, b1 + (size_t)i * FFD, nullptr, pff,
            DIM, FFD, FFD, DIM, 0,0,0,0,0,0, nullptr);
        // h = h + mid @ w2 + b2
        tgemm_k<false,true,true,false,false><<<dim3(DIM/128, M/128, 1), 256, TG_SMEM>>>(
            pff, w2 + (size_t)i * FFD * DIM, b2 + (size_t)i * DIM, ph, ph,
            FFD, DIM, DIM, FFD, 0,0,0,0,0,0, nullptr);
    }

    // logits = h @ logits_w + logits_b
    tgemm_k<false,true,false,false,false><<<dim3(VOCAB/128, M/128, 1), 256, TG_SMEM>>>(
        ph, lw, lb, nullptr, out_logits,
        DIM, VOCAB, VOCAB, DIM, 0,0,0,0,0,0, nullptr);

    // ---------------- memory network ----------------
    const int MR = DEPTH * BB * LMEMN;    // 2048 rows of lmem
    // nl = LN(lmem)  (no affine)
    ln_k<<<MR, 256>>>(lmem, nullptr, nullptr, pn);
    // q = nl @ mem_wq, then per-head softmax over DH (scaled first)
    tgemm_k<false,false,false,false,false><<<dim3(DIM/128, MR/128, 1), 256, TG_SMEM>>>(
        pn, mwq, nullptr, nullptr, pq,
        DIM, DIM, DIM, DIM, 0,0,0,0,0,0, nullptr);
    qsoftmax_k<<<MR, 256>>>(pq);
    // kv_in = [nl | mem | hiddens]  per (m,b)
    for (int i = 0; i < DEPTH; i++)
        for (int b = 0; b < BB; b++) {
            const int mb = i * BB + b;
            float* dst = pkvin + (size_t)mb * KVL * DIM;
            cudaMemcpyAsync(dst, pn + (size_t)mb * LMEMN * DIM,
                            sizeof(float) * LMEMN * DIM, cudaMemcpyDeviceToDevice);
            cudaMemcpyAsync(dst + (size_t)LMEMN * DIM,
                            mem + (size_t)mb * MEMN * DIM,
                            sizeof(float) * MEMN * DIM, cudaMemcpyDeviceToDevice);
            cudaMemcpyAsync(dst + (size_t)(LMEMN + MEMN) * DIM,
                            out_nmem + (size_t)mb * MEMN * DIM,
                            sizeof(float) * MEMN * DIM, cudaMemcpyDeviceToDevice);
        }
    // KV = kv_in @ mem_wkv
    tgemm_k<false,false,false,false,false><<<dim3(2*DIM/128, DEPTH*BB*KVL/128, 1), 256, TG_SMEM>>>(
        pkvin, mwkv, nullptr, nullptr, pkv,
        DIM, 2*DIM, 2*DIM, DIM, 0,0,0,0,0,0, nullptr);
    // column softmax stats for k, then ctx = softk^T v, out = q @ ctx
    kcolstat_k<<<dim3(DIM/32, DEPTH*BB), 256>>>(pkv, pkm, pki);
    ctx_k<<<DEPTH*BB*HEADS, 256>>>(pkv, pkm, pki, pctx);
    memout_k<<<dim3(DEPTH*BB*HEADS, LMEMN/64), 128>>>(pq, pctx, ptmp);
    // next_lmem = out @ mem_wo * rezero + lmem
    tgemm_k<false,false,true,false,true><<<dim3(DIM/128, MR/128, 1), 256, TG_SMEM>>>(
        ptmp, mwo, nullptr, lmem, out_nlmem,
        DIM, DIM, DIM, DIM, 0,0,0,0,0,0, rez);
}